// round 13
// baseline (speedup 1.0000x reference)
#include <cuda_runtime.h>
#include <cuda_fp16.h>
#include <stdint.h>
#include <math.h>

#define S_LEN 2048
#define B_SZ 2
#define D_MODEL 2048
#define NH 16
#define HD 128
#define MROWS (B_SZ * S_LEN)
#define KDIM 2048

// ---------------- scratch (static device allocations: allowed) ----------------
__device__ float g_cos[S_LEN * (HD / 2)];
__device__ float g_sin[S_LEN * (HD / 2)];

__device__ __half g_x16[(size_t)MROWS * D_MODEL];
__device__ __half g_o16[(size_t)MROWS * D_MODEL];
__device__ __half g_wq16[(size_t)D_MODEL * D_MODEL];
__device__ __half g_wk16[(size_t)D_MODEL * D_MODEL];
__device__ __half g_wv16[(size_t)D_MODEL * D_MODEL];
__device__ __half g_wo16[(size_t)D_MODEL * D_MODEL];

// fp16 attention operands (written by QKV GEMM epilogue, rope applied)
__device__ __half g_qh2a[(size_t)MROWS * D_MODEL];   // q hi
__device__ __half g_ql2a[(size_t)MROWS * D_MODEL];   // q lo
__device__ __half g_k16[(size_t)MROWS * D_MODEL];    // k
__device__ __half g_v16[(size_t)MROWS * D_MODEL];    // v

// ======================= low-level helpers ====================================
__device__ __forceinline__ uint32_t smem_u32(const void* p) {
    uint32_t a;
    asm("{ .reg .u64 t; cvta.to.shared.u64 t, %1; cvt.u32.u64 %0, t; }" : "=r"(a) : "l"(p));
    return a;
}
__device__ __forceinline__ void cp16(uint32_t dst, const void* src) {
    asm volatile("cp.async.cg.shared.global [%0], [%1], 16;" :: "r"(dst), "l"(src));
}
__device__ __forceinline__ void cp_commit() {
    asm volatile("cp.async.commit_group;" ::: "memory");
}
#define CP_WAIT(n) asm volatile("cp.async.wait_group " #n ";" ::: "memory")

__device__ __forceinline__ void ldsm_x4(uint32_t* r, uint32_t addr) {
    asm volatile("ldmatrix.sync.aligned.m8n8.x4.shared.b16 {%0,%1,%2,%3}, [%4];"
                 : "=r"(r[0]), "=r"(r[1]), "=r"(r[2]), "=r"(r[3]) : "r"(addr));
}
__device__ __forceinline__ void ldsm_x4_t(uint32_t* r, uint32_t addr) {
    asm volatile("ldmatrix.sync.aligned.m8n8.x4.trans.shared.b16 {%0,%1,%2,%3}, [%4];"
                 : "=r"(r[0]), "=r"(r[1]), "=r"(r[2]), "=r"(r[3]) : "r"(addr));
}
__device__ __forceinline__ void mma_f16(float* d, const uint32_t* a, const uint32_t* b) {
    asm volatile(
        "mma.sync.aligned.m16n8k16.row.col.f32.f16.f16.f32 "
        "{%0,%1,%2,%3}, {%4,%5,%6,%7}, {%8,%9}, {%0,%1,%2,%3};"
        : "+f"(d[0]), "+f"(d[1]), "+f"(d[2]), "+f"(d[3])
        : "r"(a[0]), "r"(a[1]), "r"(a[2]), "r"(a[3]), "r"(b[0]), "r"(b[1]));
}

#define SWZ(x) ((x) ^ (((x) >> 3) & 0x70))
#define SWZ256(x) ((x) ^ (((x) >> 4) & 0x70))

// =========== fp16 1-pass GEMM: 128 threads, warp tile 64x64, 3-stage =========
#define GBM 128
#define GBN 128
#define NCHUNK (KDIM / 64)
#define TILE_B (GBM * 128)        // 16KB per operand tile
#define STAGE_B (2 * TILE_B)      // 32KB per stage (A + B)
#define NSTAGE 3
#define GEMM_SMEM (NSTAGE * STAGE_B)   // 98304; 2 CTAs/SM -> 192KB

__device__ __forceinline__ void gemm_issue1(
    const __half* Ah, const __half* Bh,
    uint32_t sb0, int m0, int n0, int tid, int c, int s)
{
    const uint32_t st = sb0 + (uint32_t)s * STAGE_B;
    const size_t kb = (size_t)c * 128;
#pragma unroll
    for (int i = 0; i < 8; i++) {
        const int idx = i * 128 + tid;
        const int r = idx >> 3;
        const int lq = idx & 7;
        const uint32_t dsw = SWZ((uint32_t)(r * 128 + lq * 16));
        cp16(st + dsw,          (const char*)Ah + (size_t)(m0 + r) * (KDIM * 2) + kb + (size_t)lq * 16);
        cp16(st + TILE_B + dsw, (const char*)Bh + (size_t)(n0 + r) * (KDIM * 2) + kb + (size_t)lq * 16);
    }
    cp_commit();
}

__device__ __forceinline__ void gemm_core(
    float acc[4][8][4],
    const __half* Ah, const __half* Bh,
    uint32_t sb0, int m0, int n0)
{
    const int tid = threadIdx.x;
    const int w = tid >> 5;
    const int lane = tid & 31;
    const int m_base = (w >> 1) * 64;
    const int n_base = (w & 1) * 64;

#pragma unroll
    for (int i = 0; i < 4; i++) {
#pragma unroll
        for (int j = 0; j < 8; j++) {
#pragma unroll
            for (int e = 0; e < 4; e++) { acc[i][j][e] = 0.f; }
        }
    }

    gemm_issue1(Ah, Bh, sb0, m0, n0, tid, 0, 0);
    gemm_issue1(Ah, Bh, sb0, m0, n0, tid, 1, 1);
    gemm_issue1(Ah, Bh, sb0, m0, n0, tid, 2, 2);

    const int g8 = lane >> 3;
    const int r8 = lane & 7;
    const int rowoff = (g8 & 1) * 8 + r8;
    const int qhi = g8 >> 1;

    for (int c = 0; c < NCHUNK; c++) {
        const int s = c % NSTAGE;
        CP_WAIT(2);
        __syncthreads();
        const uint32_t sA = sb0 + (uint32_t)s * STAGE_B;
        const uint32_t sB = sA + TILE_B;

#pragma unroll
        for (int ks = 0; ks < 4; ks++) {
            const int quad = ks * 2 + qhi;
            uint32_t ah[4][4], bh[8][2];
#pragma unroll
            for (int mi = 0; mi < 4; mi++) {
                const uint32_t off = SWZ((uint32_t)((m_base + mi * 16 + rowoff) * 128 + quad * 16));
                ldsm_x4(ah[mi], sA + off);
            }
#pragma unroll
            for (int p = 0; p < 4; p++) {
                const uint32_t off = SWZ((uint32_t)((n_base + p * 16 + rowoff) * 128 + quad * 16));
                uint32_t t[4];
                ldsm_x4(t, sB + off);
                bh[2 * p][0] = t[0]; bh[2 * p][1] = t[2];
                bh[2 * p + 1][0] = t[1]; bh[2 * p + 1][1] = t[3];
            }
#pragma unroll
            for (int mi = 0; mi < 4; mi++) {
#pragma unroll
                for (int ni = 0; ni < 8; ni++) {
                    mma_f16(acc[mi][ni], ah[mi], bh[ni]);
                }
            }
        }
        __syncthreads();
        if (c + NSTAGE < NCHUNK) {
            gemm_issue1(Ah, Bh, sb0, m0, n0, tid, c + NSTAGE, s);
        } else {
            cp_commit();   // keep group accounting uniform
        }
    }
}

// ---- fused QKV projection: epilogue applies RoPE (q,k) + fp16 rounding ------
__global__ __launch_bounds__(128) void gemm_qkv(const __half* __restrict__ Ah)
{
    extern __shared__ char smem[];
    const uint32_t sb0 = smem_u32(smem);

    const int nb = blockIdx.x;
    const int which = nb >> 4;               // 0=q, 1=k, 2=v
    const int n0 = (nb & 15) * GBN;
    const __half* Bh = (which == 0) ? g_wq16 : ((which == 1) ? g_wk16 : g_wv16);
    const int m0 = blockIdx.y * GBM;

    float acc[4][8][4];
    gemm_core(acc, Ah, Bh, sb0, m0, n0);

    const int w = threadIdx.x >> 5;
    const int lane = threadIdx.x & 31;
    const int m_base = (w >> 1) * 64;
    const int n_base = (w & 1) * 64;
    const int erow = lane >> 2;
    const int ecol = (lane & 3) * 2;

#pragma unroll
    for (int mi = 0; mi < 4; mi++) {
#pragma unroll
        for (int ni = 0; ni < 8; ni++) {
            const int row = m0 + m_base + mi * 16 + erow;
            const int col = n0 + n_base + ni * 8 + ecol;     // even
            float a0 = acc[mi][ni][0], a1 = acc[mi][ni][1];
            float b0 = acc[mi][ni][2], b1 = acc[mi][ni][3];
            if (which < 2) {    // RoPE on q, k
                const int i = (col & 127) >> 1;
                const int s1 = row & (S_LEN - 1);
                const int s2 = (row + 8) & (S_LEN - 1);
                float c1 = g_cos[(s1 << 6) + i], sn1 = g_sin[(s1 << 6) + i];
                float c2 = g_cos[(s2 << 6) + i], sn2 = g_sin[(s2 << 6) + i];
                float t0 = a0 * c1 - a1 * sn1;
                float t1 = a0 * sn1 + a1 * c1;
                a0 = t0; a1 = t1;
                t0 = b0 * c2 - b1 * sn2;
                t1 = b0 * sn2 + b1 * c2;
                b0 = t0; b1 = t1;
            }
            const size_t off0 = (size_t)row * D_MODEL + col;
            const size_t off1 = (size_t)(row + 8) * D_MODEL + col;
            __half ha0 = __float2half_rn(a0);
            __half ha1 = __float2half_rn(a1);
            __half hb0 = __float2half_rn(b0);
            __half hb1 = __float2half_rn(b1);
            ushort2 va, vb;
            va.x = __half_as_ushort(ha0); va.y = __half_as_ushort(ha1);
            vb.x = __half_as_ushort(hb0); vb.y = __half_as_ushort(hb1);
            if (which == 0) {
                ((ushort2*)g_qh2a)[off0 >> 1] = va;
                ((ushort2*)g_qh2a)[off1 >> 1] = vb;
                __half la0 = __float2half_rn(a0 - __half2float(ha0));
                __half la1 = __float2half_rn(a1 - __half2float(ha1));
                __half lb0 = __float2half_rn(b0 - __half2float(hb0));
                __half lb1 = __float2half_rn(b1 - __half2float(hb1));
                ushort2 wa, wb;
                wa.x = __half_as_ushort(la0); wa.y = __half_as_ushort(la1);
                wb.x = __half_as_ushort(lb0); wb.y = __half_as_ushort(lb1);
                ((ushort2*)g_ql2a)[off0 >> 1] = wa;
                ((ushort2*)g_ql2a)[off1 >> 1] = wb;
            } else if (which == 1) {
                ((ushort2*)g_k16)[off0 >> 1] = va;
                ((ushort2*)g_k16)[off1 >> 1] = vb;
            } else {
                ((ushort2*)g_v16)[off0 >> 1] = va;
                ((ushort2*)g_v16)[off1 >> 1] = vb;
            }
        }
    }
}

// ---- output projection: fp32 epilogue to d_out ------------------------------
__global__ __launch_bounds__(128) void gemm_out(
    const __half* __restrict__ Ah,
    const __half* __restrict__ Bh, float* __restrict__ C)
{
    extern __shared__ char smem[];
    const uint32_t sb0 = smem_u32(smem);
    const int n0 = blockIdx.x * GBN;
    const int m0 = blockIdx.y * GBM;

    float acc[4][8][4];
    gemm_core(acc, Ah, Bh, sb0, m0, n0);

    const int w = threadIdx.x >> 5;
    const int lane = threadIdx.x & 31;
    const int m_base = (w >> 1) * 64;
    const int n_base = (w & 1) * 64;
    const int erow = lane >> 2;
    const int ecol = (lane & 3) * 2;
#pragma unroll
    for (int mi = 0; mi < 4; mi++) {
#pragma unroll
        for (int ni = 0; ni < 8; ni++) {
            const int row = m0 + m_base + mi * 16 + erow;
            const int col = n0 + n_base + ni * 8 + ecol;
            *(float2*)(C + (size_t)row * D_MODEL + col) =
                make_float2(acc[mi][ni][0], acc[mi][ni][1]);
            *(float2*)(C + (size_t)(row + 8) * D_MODEL + col) =
                make_float2(acc[mi][ni][2], acc[mi][ni][3]);
        }
    }
}

// ---------------- fused fp32 -> fp16 convert (x + 4 weights) ----------------
#define XN4 (MROWS * D_MODEL / 4)
#define WN4 (D_MODEL * D_MODEL / 4)

__global__ void cvt_all_kernel(const float* __restrict__ x,
                               const float* __restrict__ wq,
                               const float* __restrict__ wk,
                               const float* __restrict__ wv,
                               const float* __restrict__ wo)
{
    int i = blockIdx.x * blockDim.x + threadIdx.x;
    const float* src;
    __half* dst;
    int j = i;
    if (j < XN4) { src = x; dst = g_x16; }
    else {
        j -= XN4;
        if (j < WN4) { src = wq; dst = g_wq16; }
        else {
            j -= WN4;
            if (j < WN4) { src = wk; dst = g_wk16; }
            else {
                j -= WN4;
                if (j < WN4) { src = wv; dst = g_wv16; }
                else {
                    j -= WN4;
                    if (j >= WN4) return;
                    src = wo; dst = g_wo16;
                }
            }
        }
    }
    float4 f = ((const float4*)src)[j];
    ushort4 hv;
    hv.x = __half_as_ushort(__float2half_rn(f.x));
    hv.y = __half_as_ushort(__float2half_rn(f.y));
    hv.z = __half_as_ushort(__float2half_rn(f.z));
    hv.w = __half_as_ushort(__float2half_rn(f.w));
    ((ushort4*)dst)[j] = hv;
}

// ---------------- RoPE table (double precision angles) ----------------
__global__ void rope_table_kernel() {
    int idx = blockIdx.x * blockDim.x + threadIdx.x;
    if (idx >= S_LEN * (HD / 2)) return;
    int s = idx >> 6;
    int i = idx & 63;
    double freq = exp(-log(10000.0) * (double)(2 * i) / (double)HD);
    double ang = (double)s * freq;
    g_cos[idx] = (float)cos(ang);
    g_sin[idx] = (float)sin(ang);
}

// ============== Flash attention (causal) fp16: QK 2-pass, PV 1-pass ==========
#define FAQ 64
#define FAK 32
#define FA_QHI 0
#define FA_QLO 16384
#define FA_STG 32768
#define FA_TILE 8192
#define FA_STAGE (2 * FA_TILE)
#define FA_SMEM (FA_STG + 2 * FA_STAGE)   // 65536

__device__ __forceinline__ void fa_issue_stage(
    uint32_t sb, int s, int k0, int tid,
    const __half* kp, const __half* vp)
{
    const uint32_t st = sb + FA_STG + (uint32_t)s * FA_STAGE;
#pragma unroll
    for (int i = 0; i < 4; i++) {
        int idx = i * 128 + tid;
        int row = idx >> 4, ch = idx & 15;
        uint32_t dsw = SWZ256((uint32_t)(row * 256 + ch * 16));
        const char* srck = (const char*)kp + (size_t)(k0 + row) * (D_MODEL * 2) + (size_t)ch * 16;
        const char* srcv = (const char*)vp + (size_t)(k0 + row) * (D_MODEL * 2) + (size_t)ch * 16;
        cp16(st + dsw,           srck);
        cp16(st + FA_TILE + dsw, srcv);
    }
    cp_commit();
}

__global__ __launch_bounds__(128, 2) void flash_attn_mma() {
    extern __shared__ char smraw[];
    const uint32_t sb = smem_u32(smraw);
    const int tid = threadIdx.x;
    const int lane = tid & 31;
    const int w = tid >> 5;
    const int qt = (int)gridDim.x - 1 - (int)blockIdx.x;
    const int bh = blockIdx.y;
    const int b = bh >> 4, h = bh & 15;
    const int q0 = qt * FAQ;
    const int n_kt = 2 * qt + 2;

    const size_t base = (size_t)b * S_LEN * D_MODEL + (size_t)h * HD;
    const __half* qhp = g_qh2a + base;
    const __half* qlp = g_ql2a + base;
    const __half* kp  = g_k16 + base;
    const __half* vp  = g_v16 + base;
    __half* oph = g_o16 + base;

#pragma unroll
    for (int i = 0; i < 8; i++) {
        int idx = i * 128 + tid;
        int row = idx >> 4, ch = idx & 15;
        uint32_t dsw = SWZ256((uint32_t)(row * 256 + ch * 16));
        const char* srch = (const char*)qhp + (size_t)(q0 + row) * (D_MODEL * 2) + (size_t)ch * 16;
        const char* srcl = (const char*)qlp + (size_t)(q0 + row) * (D_MODEL * 2) + (size_t)ch * 16;
        cp16(sb + FA_QHI + dsw, srch);
        cp16(sb + FA_QLO + dsw, srcl);
    }
    cp_commit();
    fa_issue_stage(sb, 0, 0, tid, kp, vp);
    fa_issue_stage(sb, 1, FAK, tid, kp, vp);

    const int g8 = lane >> 3;
    const int r8 = lane & 7;
    const int rowoff = (g8 & 1) * 8 + r8;
    const int qsel = g8 >> 1;

    float oacc[16][4];
#pragma unroll
    for (int t = 0; t < 16; t++) {
#pragma unroll
        for (int e = 0; e < 4; e++) { oacc[t][e] = 0.f; }
    }
    float m0 = -1e30f, m1 = -1e30f, l0 = 0.f, l1 = 0.f;
    const float sm_scale = 0.08838834764831843f;

    const int lrow0 = q0 + w * 16 + (lane >> 2);
    const int lcolb = (lane & 3) * 2;

    for (int kt = 0; kt < n_kt; kt++) {
        const int s = kt & 1;
        const int k0 = kt * FAK;
        CP_WAIT(1);
        __syncthreads();
        const uint32_t stg = sb + FA_STG + (uint32_t)s * FA_STAGE;

        float sacc[4][4];
#pragma unroll
        for (int t = 0; t < 4; t++) {
#pragma unroll
            for (int e = 0; e < 4; e++) { sacc[t][e] = 0.f; }
        }
#pragma unroll
        for (int ks = 0; ks < 8; ks++) {
            const int quad = ks * 2 + qsel;
            uint32_t qfh[4], qfl[4];
            const uint32_t qoff = SWZ256((uint32_t)((w * 16 + rowoff) * 256 + quad * 16));
            ldsm_x4(qfh, sb + FA_QHI + qoff);
            ldsm_x4(qfl, sb + FA_QLO + qoff);
#pragma unroll
            for (int nt = 0; nt < 2; nt++) {
                const uint32_t koff = SWZ256((uint32_t)((nt * 16 + rowoff) * 256 + quad * 16));
                uint32_t tk[4];
                ldsm_x4(tk, stg + koff);
                uint32_t b0[2], b1[2];
                b0[0] = tk[0]; b0[1] = tk[2];
                b1[0] = tk[1]; b1[1] = tk[3];
                mma_f16(sacc[nt * 2],     qfh, b0);
                mma_f16(sacc[nt * 2],     qfl, b0);
                mma_f16(sacc[nt * 2 + 1], qfh, b1);
                mma_f16(sacc[nt * 2 + 1], qfl, b1);
            }
        }

        const int need_mask = (k0 + FAK - 1 > q0 + w * 16) ? 1 : 0;
#pragma unroll
        for (int t = 0; t < 4; t++) {
#pragma unroll
            for (int e = 0; e < 4; e++) {
                float sv = sacc[t][e] * sm_scale;
                if (need_mask) {
                    int col = k0 + t * 8 + lcolb + (e & 1);
                    int row = lrow0 + ((e >> 1) & 1) * 8;
                    if (col > row) { sv = -1e30f; }
                }
                sacc[t][e] = sv;
            }
        }

        float rm0 = sacc[0][0], rm1 = sacc[0][2];
#pragma unroll
        for (int t = 0; t < 4; t++) {
            rm0 = fmaxf(rm0, fmaxf(sacc[t][0], sacc[t][1]));
            rm1 = fmaxf(rm1, fmaxf(sacc[t][2], sacc[t][3]));
        }
        rm0 = fmaxf(rm0, __shfl_xor_sync(0xffffffffu, rm0, 1));
        rm0 = fmaxf(rm0, __shfl_xor_sync(0xffffffffu, rm0, 2));
        rm1 = fmaxf(rm1, __shfl_xor_sync(0xffffffffu, rm1, 1));
        rm1 = fmaxf(rm1, __shfl_xor_sync(0xffffffffu, rm1, 2));
        float mn0 = fmaxf(m0, rm0);
        float mn1 = fmaxf(m1, rm1);
        float alpha0 = expf(m0 - mn0);
        float alpha1 = expf(m1 - mn1);
        float rs0 = 0.f, rs1 = 0.f;
#pragma unroll
        for (int t = 0; t < 4; t++) {
            float p0 = expf(sacc[t][0] - mn0);
            float p1 = expf(sacc[t][1] - mn0);
            float p2 = expf(sacc[t][2] - mn1);
            float p3 = expf(sacc[t][3] - mn1);
            rs0 += p0 + p1;
            rs1 += p2 + p3;
            sacc[t][0] = p0; sacc[t][1] = p1;
            sacc[t][2] = p2; sacc[t][3] = p3;
        }
        rs0 += __shfl_xor_sync(0xffffffffu, rs0, 1);
        rs0 += __shfl_xor_sync(0xffffffffu, rs0, 2);
        rs1 += __shfl_xor_sync(0xffffffffu, rs1, 1);
        rs1 += __shfl_xor_sync(0xffffffffu, rs1, 2);
        l0 = l0 * alpha0 + rs0;
        l1 = l1 * alpha1 + rs1;
        m0 = mn0; m1 = mn1;
#pragma unroll
        for (int t = 0; t < 16; t++) {
            oacc[t][0] *= alpha0; oacc[t][1] *= alpha0;
            oacc[t][2] *= alpha1; oacc[t][3] *= alpha1;
        }

        uint32_t pf[2][4];
#pragma unroll
        for (int j = 0; j < 2; j++) {
#pragma unroll
            for (int idx = 0; idx < 4; idx++) {
                int st = 2 * j + (idx >> 1);
                int rp = (idx & 1) * 2;
                __half p0 = __float2half_rn(sacc[st][rp]);
                __half p1 = __float2half_rn(sacc[st][rp + 1]);
                pf[j][idx] = (uint32_t)__half_as_ushort(p0)
                           | ((uint32_t)__half_as_ushort(p1) << 16);
            }
        }

        const int vrow_base = (lane & 7) + ((lane >> 3) & 1) * 8;
        const int vcol_base = ((lane >> 4) & 1) * 16;
#pragma unroll
        for (int j = 0; j < 2; j++) {
#pragma unroll
            for (int nt = 0; nt < 8; nt++) {
                const int vr = j * 16 + vrow_base;
                const int vcb = nt * 32 + vcol_base;
                const uint32_t voff = SWZ256((uint32_t)(vr * 256 + vcb));
                uint32_t tv[4];
                ldsm_x4_t(tv, stg + FA_TILE + voff);
                uint32_t b0[2], b1[2];
                b0[0] = tv[0]; b0[1] = tv[1];
                b1[0] = tv[2]; b1[1] = tv[3];
                mma_f16(oacc[nt * 2],     pf[j], b0);
                mma_f16(oacc[nt * 2 + 1], pf[j], b1);
            }
        }

        __syncthreads();
        if (kt + 2 < n_kt) {
            fa_issue_stage(sb, s, (kt + 2) * FAK, tid, kp, vp);
        } else {
            cp_commit();
        }
    }

    const float inv0 = 1.f / l0;
    const float inv1 = 1.f / l1;
#pragma unroll
    for (int t = 0; t < 16; t++) {
        const int col = t * 8 + lcolb;
        const size_t off0 = (size_t)lrow0 * D_MODEL + col;
        const size_t off1 = (size_t)(lrow0 + 8) * D_MODEL + col;
        ushort2 a, bq;
        a.x = __half_as_ushort(__float2half_rn(oacc[t][0] * inv0));
        a.y = __half_as_ushort(__float2half_rn(oacc[t][1] * inv0));
        bq.x = __half_as_ushort(__float2half_rn(oacc[t][2] * inv1));
        bq.y = __half_as_ushort(__float2half_rn(oacc[t][3] * inv1));
        ((ushort2*)oph)[off0 >> 1] = a;
        ((ushort2*)oph)[off1 >> 1] = bq;
    }
}

// ======================= host side =======================
extern "C" void kernel_launch(void* const* d_in, const int* in_sizes, int n_in,
                              void* d_out, int out_size) {
    const float* x  = (const float*)d_in[0];
    const float* wq = (const float*)d_in[1];
    const float* wk = (const float*)d_in[2];
    const float* wv = (const float*)d_in[3];
    const float* wo = (const float*)d_in[4];
    float* out = (float*)d_out;

    __half *x16, *o16, *wo16;
    cudaGetSymbolAddress((void**)&x16, g_x16);
    cudaGetSymbolAddress((void**)&o16, g_o16);
    cudaGetSymbolAddress((void**)&wo16, g_wo16);

    rope_table_kernel<<<(S_LEN * (HD / 2) + 255) / 256, 256>>>();

    const int total4 = XN4 + 4 * WN4;
    cvt_all_kernel<<<(total4 + 255) / 256, 256>>>(x, wq, wk, wv, wo);

    cudaFuncSetAttribute(gemm_qkv, cudaFuncAttributeMaxDynamicSharedMemorySize, GEMM_SMEM);
    cudaFuncSetAttribute(gemm_out, cudaFuncAttributeMaxDynamicSharedMemorySize, GEMM_SMEM);

    gemm_qkv<<<dim3(48, MROWS / GBM), 128, GEMM_SMEM>>>(x16);

    cudaFuncSetAttribute(flash_attn_mma, cudaFuncAttributeMaxDynamicSharedMemorySize, FA_SMEM);
    flash_attn_mma<<<dim3(S_LEN / FAQ, B_SZ * NH), 128, FA_SMEM>>>();

    gemm_out<<<dim3(16, MROWS / GBM), 128, GEMM_SMEM>>>(o16, wo16, out);
}

// round 15
// speedup vs baseline: 1.0771x; 1.0771x over previous
#include <cuda_runtime.h>
#include <cuda_fp16.h>
#include <stdint.h>
#include <math.h>

#define S_LEN 2048
#define B_SZ 2
#define D_MODEL 2048
#define NH 16
#define HD 128
#define MROWS (B_SZ * S_LEN)
#define KDIM 2048

// ---------------- scratch (static device allocations: allowed) ----------------
__device__ float g_cos[S_LEN * (HD / 2)];
__device__ float g_sin[S_LEN * (HD / 2)];

__device__ __half g_x16[(size_t)MROWS * D_MODEL];
__device__ __half g_o16[(size_t)MROWS * D_MODEL];
__device__ __half g_wq16[(size_t)D_MODEL * D_MODEL];
__device__ __half g_wk16[(size_t)D_MODEL * D_MODEL];
__device__ __half g_wv16[(size_t)D_MODEL * D_MODEL];
__device__ __half g_wo16[(size_t)D_MODEL * D_MODEL];

// fp16 attention operands (written by QKV GEMM epilogue, rope applied)
__device__ __half g_qh2a[(size_t)MROWS * D_MODEL];   // q hi
__device__ __half g_ql2a[(size_t)MROWS * D_MODEL];   // q lo
__device__ __half g_k16[(size_t)MROWS * D_MODEL];    // k
__device__ __half g_v16[(size_t)MROWS * D_MODEL];    // v

// ======================= low-level helpers ====================================
__device__ __forceinline__ uint32_t smem_u32(const void* p) {
    uint32_t a;
    asm("{ .reg .u64 t; cvta.to.shared.u64 t, %1; cvt.u32.u64 %0, t; }" : "=r"(a) : "l"(p));
    return a;
}
__device__ __forceinline__ void cp16(uint32_t dst, const void* src) {
    asm volatile("cp.async.cg.shared.global [%0], [%1], 16;" :: "r"(dst), "l"(src));
}
__device__ __forceinline__ void cp_commit() {
    asm volatile("cp.async.commit_group;" ::: "memory");
}
#define CP_WAIT(n) asm volatile("cp.async.wait_group " #n ";" ::: "memory")

__device__ __forceinline__ void ldsm_x4(uint32_t* r, uint32_t addr) {
    asm volatile("ldmatrix.sync.aligned.m8n8.x4.shared.b16 {%0,%1,%2,%3}, [%4];"
                 : "=r"(r[0]), "=r"(r[1]), "=r"(r[2]), "=r"(r[3]) : "r"(addr));
}
__device__ __forceinline__ void ldsm_x4_t(uint32_t* r, uint32_t addr) {
    asm volatile("ldmatrix.sync.aligned.m8n8.x4.trans.shared.b16 {%0,%1,%2,%3}, [%4];"
                 : "=r"(r[0]), "=r"(r[1]), "=r"(r[2]), "=r"(r[3]) : "r"(addr));
}
__device__ __forceinline__ void mma_f16(float* d, const uint32_t* a, const uint32_t* b) {
    asm volatile(
        "mma.sync.aligned.m16n8k16.row.col.f32.f16.f16.f32 "
        "{%0,%1,%2,%3}, {%4,%5,%6,%7}, {%8,%9}, {%0,%1,%2,%3};"
        : "+f"(d[0]), "+f"(d[1]), "+f"(d[2]), "+f"(d[3])
        : "r"(a[0]), "r"(a[1]), "r"(a[2]), "r"(a[3]), "r"(b[0]), "r"(b[1]));
}

#define SWZ(x) ((x) ^ (((x) >> 3) & 0x70))
#define SWZ256(x) ((x) ^ (((x) >> 4) & 0x70))

// =========== fp16 1-pass GEMM (R11 config): 256 thr, warp 64x32, 2-stage =====
#define GBM 128
#define GBN 128
#define NCHUNK (KDIM / 64)
#define TILE_B (GBM * 128)
#define STAGE_B (2 * TILE_B)      // A, B tiles
#define GEMM_SMEM (2 * STAGE_B)   // 65536

__device__ __forceinline__ void gemm_issue1(
    const __half* Ah, const __half* Bh,
    uint32_t sb0, int m0, int n0, int tid, int c, int s)
{
    const uint32_t st = sb0 + (uint32_t)s * STAGE_B;
    const size_t kb = (size_t)c * 128;
    const int lq = tid & 7;
#pragma unroll
    for (int i = 0; i < 4; i++) {
        const int r = (tid + i * 256) >> 3;
        const uint32_t dsw = SWZ((uint32_t)(r * 128 + lq * 16));
        const size_t arow = (size_t)(m0 + r) * (KDIM * 2) + kb + (size_t)lq * 16;
        const size_t brow = (size_t)(n0 + r) * (KDIM * 2) + kb + (size_t)lq * 16;
        cp16(st + dsw,          (const char*)Ah + arow);
        cp16(st + TILE_B + dsw, (const char*)Bh + brow);
    }
    cp_commit();
}

__device__ __forceinline__ void gemm_core(
    float acc[4][4][4],
    const __half* Ah, const __half* Bh,
    uint32_t sb0, int m0, int n0)
{
    const int tid = threadIdx.x;
    const int wid = tid >> 5;
    const int lane = tid & 31;
    const int m_base = (wid >> 2) * 64;
    const int n_base = (wid & 3) * 32;

#pragma unroll
    for (int i = 0; i < 4; i++) {
#pragma unroll
        for (int j = 0; j < 4; j++) {
#pragma unroll
            for (int e = 0; e < 4; e++) { acc[i][j][e] = 0.f; }
        }
    }

    gemm_issue1(Ah, Bh, sb0, m0, n0, tid, 0, 0);
    gemm_issue1(Ah, Bh, sb0, m0, n0, tid, 1, 1);

    const int g8 = lane >> 3;
    const int r8 = lane & 7;
    const int rowoff = (g8 & 1) * 8 + r8;
    const int qhi = g8 >> 1;

    for (int c = 0; c < NCHUNK; c++) {
        const int s = c & 1;
        CP_WAIT(1);
        __syncthreads();
        const uint32_t sA = sb0 + (uint32_t)s * STAGE_B;
        const uint32_t sB = sA + TILE_B;

#pragma unroll
        for (int ks = 0; ks < 4; ks++) {
            const int quad = ks * 2 + qhi;
            uint32_t ah[4][4], bh[4][2];
#pragma unroll
            for (int mi = 0; mi < 4; mi++) {
                const uint32_t off = SWZ((uint32_t)((m_base + mi * 16 + rowoff) * 128 + quad * 16));
                ldsm_x4(ah[mi], sA + off);
            }
#pragma unroll
            for (int p = 0; p < 2; p++) {
                const uint32_t off = SWZ((uint32_t)((n_base + p * 16 + rowoff) * 128 + quad * 16));
                uint32_t t[4];
                ldsm_x4(t, sB + off);
                bh[2 * p][0] = t[0]; bh[2 * p][1] = t[2];
                bh[2 * p + 1][0] = t[1]; bh[2 * p + 1][1] = t[3];
            }
#pragma unroll
            for (int mi = 0; mi < 4; mi++) {
#pragma unroll
                for (int ni = 0; ni < 4; ni++) {
                    mma_f16(acc[mi][ni], ah[mi], bh[ni]);
                }
            }
        }
        __syncthreads();
        if (c + 2 < NCHUNK) {
            gemm_issue1(Ah, Bh, sb0, m0, n0, tid, c + 2, s);
        }
    }
}

// ---- fused QKV projection: epilogue applies RoPE (q,k) + fp16 rounding ------
__global__ __launch_bounds__(256) void gemm_qkv(const __half* __restrict__ Ah)
{
    extern __shared__ char smem[];
    const uint32_t sb0 = smem_u32(smem);

    const int nb = blockIdx.x;
    const int which = nb >> 4;               // 0=q, 1=k, 2=v
    const int n0 = (nb & 15) * GBN;
    const __half* Bh = (which == 0) ? g_wq16 : ((which == 1) ? g_wk16 : g_wv16);
    const int m0 = blockIdx.y * GBM;

    float acc[4][4][4];
    gemm_core(acc, Ah, Bh, sb0, m0, n0);

    const int wid = threadIdx.x >> 5;
    const int lane = threadIdx.x & 31;
    const int m_base = (wid >> 2) * 64;
    const int n_base = (wid & 3) * 32;
    const int erow = lane >> 2;
    const int ecol = (lane & 3) * 2;

#pragma unroll
    for (int mi = 0; mi < 4; mi++) {
#pragma unroll
        for (int ni = 0; ni < 4; ni++) {
            const int row = m0 + m_base + mi * 16 + erow;
            const int col = n0 + n_base + ni * 8 + ecol;     // even
            float a0 = acc[mi][ni][0], a1 = acc[mi][ni][1];
            float b0 = acc[mi][ni][2], b1 = acc[mi][ni][3];
            if (which < 2) {    // RoPE on q, k
                const int i = (col & 127) >> 1;
                const int s1 = row & (S_LEN - 1);
                const int s2 = (row + 8) & (S_LEN - 1);
                float c1 = g_cos[(s1 << 6) + i], sn1 = g_sin[(s1 << 6) + i];
                float c2 = g_cos[(s2 << 6) + i], sn2 = g_sin[(s2 << 6) + i];
                float t0 = a0 * c1 - a1 * sn1;
                float t1 = a0 * sn1 + a1 * c1;
                a0 = t0; a1 = t1;
                t0 = b0 * c2 - b1 * sn2;
                t1 = b0 * sn2 + b1 * c2;
                b0 = t0; b1 = t1;
            }
            const size_t off0 = (size_t)row * D_MODEL + col;
            const size_t off1 = (size_t)(row + 8) * D_MODEL + col;
            __half ha0 = __float2half_rn(a0);
            __half ha1 = __float2half_rn(a1);
            __half hb0 = __float2half_rn(b0);
            __half hb1 = __float2half_rn(b1);
            ushort2 va, vb;
            va.x = __half_as_ushort(ha0); va.y = __half_as_ushort(ha1);
            vb.x = __half_as_ushort(hb0); vb.y = __half_as_ushort(hb1);
            if (which == 0) {
                ((ushort2*)g_qh2a)[off0 >> 1] = va;
                ((ushort2*)g_qh2a)[off1 >> 1] = vb;
                __half la0 = __float2half_rn(a0 - __half2float(ha0));
                __half la1 = __float2half_rn(a1 - __half2float(ha1));
                __half lb0 = __float2half_rn(b0 - __half2float(hb0));
                __half lb1 = __float2half_rn(b1 - __half2float(hb1));
                ushort2 wa, wb;
                wa.x = __half_as_ushort(la0); wa.y = __half_as_ushort(la1);
                wb.x = __half_as_ushort(lb0); wb.y = __half_as_ushort(lb1);
                ((ushort2*)g_ql2a)[off0 >> 1] = wa;
                ((ushort2*)g_ql2a)[off1 >> 1] = wb;
            } else if (which == 1) {
                ((ushort2*)g_k16)[off0 >> 1] = va;
                ((ushort2*)g_k16)[off1 >> 1] = vb;
            } else {
                ((ushort2*)g_v16)[off0 >> 1] = va;
                ((ushort2*)g_v16)[off1 >> 1] = vb;
            }
        }
    }
}

// ---- output projection: fp32 epilogue to d_out ------------------------------
__global__ __launch_bounds__(256) void gemm_out(
    const __half* __restrict__ Ah,
    const __half* __restrict__ Bh, float* __restrict__ C)
{
    extern __shared__ char smem[];
    const uint32_t sb0 = smem_u32(smem);
    const int n0 = blockIdx.x * GBN;
    const int m0 = blockIdx.y * GBM;

    float acc[4][4][4];
    gemm_core(acc, Ah, Bh, sb0, m0, n0);

    const int wid = threadIdx.x >> 5;
    const int lane = threadIdx.x & 31;
    const int m_base = (wid >> 2) * 64;
    const int n_base = (wid & 3) * 32;
    const int erow = lane >> 2;
    const int ecol = (lane & 3) * 2;
#pragma unroll
    for (int mi = 0; mi < 4; mi++) {
#pragma unroll
        for (int ni = 0; ni < 4; ni++) {
            const int row = m0 + m_base + mi * 16 + erow;
            const int col = n0 + n_base + ni * 8 + ecol;
            *(float2*)(C + (size_t)row * D_MODEL + col) =
                make_float2(acc[mi][ni][0], acc[mi][ni][1]);
            *(float2*)(C + (size_t)(row + 8) * D_MODEL + col) =
                make_float2(acc[mi][ni][2], acc[mi][ni][3]);
        }
    }
}

// ---------------- fused fp32 -> fp16 convert (x + 4 weights) ----------------
#define XN4 (MROWS * D_MODEL / 4)
#define WN4 (D_MODEL * D_MODEL / 4)

__global__ void cvt_all_kernel(const float* __restrict__ x,
                               const float* __restrict__ wq,
                               const float* __restrict__ wk,
                               const float* __restrict__ wv,
                               const float* __restrict__ wo)
{
    int i = blockIdx.x * blockDim.x + threadIdx.x;
    const float* src;
    __half* dst;
    int j = i;
    if (j < XN4) { src = x; dst = g_x16; }
    else {
        j -= XN4;
        if (j < WN4) { src = wq; dst = g_wq16; }
        else {
            j -= WN4;
            if (j < WN4) { src = wk; dst = g_wk16; }
            else {
                j -= WN4;
                if (j < WN4) { src = wv; dst = g_wv16; }
                else {
                    j -= WN4;
                    if (j >= WN4) return;
                    src = wo; dst = g_wo16;
                }
            }
        }
    }
    float4 f = ((const float4*)src)[j];
    ushort4 hv;
    hv.x = __half_as_ushort(__float2half_rn(f.x));
    hv.y = __half_as_ushort(__float2half_rn(f.y));
    hv.z = __half_as_ushort(__float2half_rn(f.z));
    hv.w = __half_as_ushort(__float2half_rn(f.w));
    ((ushort4*)dst)[j] = hv;
}

// ---------------- RoPE table (double precision angles) ----------------
__global__ void rope_table_kernel() {
    int idx = blockIdx.x * blockDim.x + threadIdx.x;
    if (idx >= S_LEN * (HD / 2)) return;
    int s = idx >> 6;
    int i = idx & 63;
    double freq = exp(-log(10000.0) * (double)(2 * i) / (double)HD);
    double ang = (double)s * freq;
    g_cos[idx] = (float)cos(ang);
    g_sin[idx] = (float)sin(ang);
}

// ============== Flash attention (causal) fp16: QK 2-pass, PV 1-pass ==========
#define FAQ 64
#define FAK 32
#define FA_QHI 0
#define FA_QLO 16384
#define FA_STG 32768
#define FA_TILE 8192
#define FA_STAGE (2 * FA_TILE)
#define FA_SMEM (FA_STG + 2 * FA_STAGE)   // 65536 -> 3 CTAs/SM by smem

__device__ __forceinline__ void fa_issue_stage(
    uint32_t sb, int s, int k0, int tid,
    const __half* kp, const __half* vp)
{
    const uint32_t st = sb + FA_STG + (uint32_t)s * FA_STAGE;
#pragma unroll
    for (int i = 0; i < 4; i++) {
        int idx = i * 128 + tid;
        int row = idx >> 4, ch = idx & 15;
        uint32_t dsw = SWZ256((uint32_t)(row * 256 + ch * 16));
        const char* srck = (const char*)kp + (size_t)(k0 + row) * (D_MODEL * 2) + (size_t)ch * 16;
        const char* srcv = (const char*)vp + (size_t)(k0 + row) * (D_MODEL * 2) + (size_t)ch * 16;
        cp16(st + dsw,           srck);
        cp16(st + FA_TILE + dsw, srcv);
    }
    cp_commit();
}

__global__ __launch_bounds__(128, 3) void flash_attn_mma() {
    extern __shared__ char smraw[];
    const uint32_t sb = smem_u32(smraw);
    const int tid = threadIdx.x;
    const int lane = tid & 31;
    const int w = tid >> 5;
    const int qt = (int)gridDim.x - 1 - (int)blockIdx.x;
    const int bh = blockIdx.y;
    const int b = bh >> 4, h = bh & 15;
    const int q0 = qt * FAQ;
    const int n_kt = 2 * qt + 2;

    const size_t base = (size_t)b * S_LEN * D_MODEL + (size_t)h * HD;
    const __half* qhp = g_qh2a + base;
    const __half* qlp = g_ql2a + base;
    const __half* kp  = g_k16 + base;
    const __half* vp  = g_v16 + base;
    __half* oph = g_o16 + base;

#pragma unroll
    for (int i = 0; i < 8; i++) {
        int idx = i * 128 + tid;
        int row = idx >> 4, ch = idx & 15;
        uint32_t dsw = SWZ256((uint32_t)(row * 256 + ch * 16));
        const char* srch = (const char*)qhp + (size_t)(q0 + row) * (D_MODEL * 2) + (size_t)ch * 16;
        const char* srcl = (const char*)qlp + (size_t)(q0 + row) * (D_MODEL * 2) + (size_t)ch * 16;
        cp16(sb + FA_QHI + dsw, srch);
        cp16(sb + FA_QLO + dsw, srcl);
    }
    cp_commit();
    fa_issue_stage(sb, 0, 0, tid, kp, vp);
    fa_issue_stage(sb, 1, FAK, tid, kp, vp);

    const int g8 = lane >> 3;
    const int r8 = lane & 7;
    const int rowoff = (g8 & 1) * 8 + r8;
    const int qsel = g8 >> 1;

    float oacc[16][4];
#pragma unroll
    for (int t = 0; t < 16; t++) {
#pragma unroll
        for (int e = 0; e < 4; e++) { oacc[t][e] = 0.f; }
    }
    float m0 = -1e30f, m1 = -1e30f, l0 = 0.f, l1 = 0.f;
    const float sm_scale = 0.08838834764831843f;

    const int lrow0 = q0 + w * 16 + (lane >> 2);
    const int lcolb = (lane & 3) * 2;

    for (int kt = 0; kt < n_kt; kt++) {
        const int s = kt & 1;
        const int k0 = kt * FAK;
        CP_WAIT(1);
        __syncthreads();
        const uint32_t stg = sb + FA_STG + (uint32_t)s * FA_STAGE;

        float sacc[4][4];
#pragma unroll
        for (int t = 0; t < 4; t++) {
#pragma unroll
            for (int e = 0; e < 4; e++) { sacc[t][e] = 0.f; }
        }
#pragma unroll
        for (int ks = 0; ks < 8; ks++) {
            const int quad = ks * 2 + qsel;
            uint32_t qfh[4], qfl[4];
            const uint32_t qoff = SWZ256((uint32_t)((w * 16 + rowoff) * 256 + quad * 16));
            ldsm_x4(qfh, sb + FA_QHI + qoff);
            ldsm_x4(qfl, sb + FA_QLO + qoff);
#pragma unroll
            for (int nt = 0; nt < 2; nt++) {
                const uint32_t koff = SWZ256((uint32_t)((nt * 16 + rowoff) * 256 + quad * 16));
                uint32_t tk[4];
                ldsm_x4(tk, stg + koff);
                uint32_t b0[2], b1[2];
                b0[0] = tk[0]; b0[1] = tk[2];
                b1[0] = tk[1]; b1[1] = tk[3];
                mma_f16(sacc[nt * 2],     qfh, b0);
                mma_f16(sacc[nt * 2],     qfl, b0);
                mma_f16(sacc[nt * 2 + 1], qfh, b1);
                mma_f16(sacc[nt * 2 + 1], qfl, b1);
            }
        }

        const int need_mask = (k0 + FAK - 1 > q0 + w * 16) ? 1 : 0;
#pragma unroll
        for (int t = 0; t < 4; t++) {
#pragma unroll
            for (int e = 0; e < 4; e++) {
                float sv = sacc[t][e] * sm_scale;
                if (need_mask) {
                    int col = k0 + t * 8 + lcolb + (e & 1);
                    int row = lrow0 + ((e >> 1) & 1) * 8;
                    if (col > row) { sv = -1e30f; }
                }
                sacc[t][e] = sv;
            }
        }

        float rm0 = sacc[0][0], rm1 = sacc[0][2];
#pragma unroll
        for (int t = 0; t < 4; t++) {
            rm0 = fmaxf(rm0, fmaxf(sacc[t][0], sacc[t][1]));
            rm1 = fmaxf(rm1, fmaxf(sacc[t][2], sacc[t][3]));
        }
        rm0 = fmaxf(rm0, __shfl_xor_sync(0xffffffffu, rm0, 1));
        rm0 = fmaxf(rm0, __shfl_xor_sync(0xffffffffu, rm0, 2));
        rm1 = fmaxf(rm1, __shfl_xor_sync(0xffffffffu, rm1, 1));
        rm1 = fmaxf(rm1, __shfl_xor_sync(0xffffffffu, rm1, 2));
        float mn0 = fmaxf(m0, rm0);
        float mn1 = fmaxf(m1, rm1);
        float alpha0 = __expf(m0 - mn0);
        float alpha1 = __expf(m1 - mn1);
        float rs0 = 0.f, rs1 = 0.f;
#pragma unroll
        for (int t = 0; t < 4; t++) {
            float p0 = __expf(sacc[t][0] - mn0);
            float p1 = __expf(sacc[t][1] - mn0);
            float p2 = __expf(sacc[t][2] - mn1);
            float p3 = __expf(sacc[t][3] - mn1);
            rs0 += p0 + p1;
            rs1 += p2 + p3;
            sacc[t][0] = p0; sacc[t][1] = p1;
            sacc[t][2] = p2; sacc[t][3] = p3;
        }
        rs0 += __shfl_xor_sync(0xffffffffu, rs0, 1);
        rs0 += __shfl_xor_sync(0xffffffffu, rs0, 2);
        rs1 += __shfl_xor_sync(0xffffffffu, rs1, 1);
        rs1 += __shfl_xor_sync(0xffffffffu, rs1, 2);
        l0 = l0 * alpha0 + rs0;
        l1 = l1 * alpha1 + rs1;
        m0 = mn0; m1 = mn1;
#pragma unroll
        for (int t = 0; t < 16; t++) {
            oacc[t][0] *= alpha0; oacc[t][1] *= alpha0;
            oacc[t][2] *= alpha1; oacc[t][3] *= alpha1;
        }

        uint32_t pf[2][4];
#pragma unroll
        for (int j = 0; j < 2; j++) {
#pragma unroll
            for (int idx = 0; idx < 4; idx++) {
                int st = 2 * j + (idx >> 1);
                int rp = (idx & 1) * 2;
                __half p0 = __float2half_rn(sacc[st][rp]);
                __half p1 = __float2half_rn(sacc[st][rp + 1]);
                pf[j][idx] = (uint32_t)__half_as_ushort(p0)
                           | ((uint32_t)__half_as_ushort(p1) << 16);
            }
        }

        const int vrow_base = (lane & 7) + ((lane >> 3) & 1) * 8;
        const int vcol_base = ((lane >> 4) & 1) * 16;
#pragma unroll
        for (int j = 0; j < 2; j++) {
#pragma unroll
            for (int nt = 0; nt < 8; nt++) {
                const int vr = j * 16 + vrow_base;
                const int vcb = nt * 32 + vcol_base;
                const uint32_t voff = SWZ256((uint32_t)(vr * 256 + vcb));
                uint32_t tv[4];
                ldsm_x4_t(tv, stg + FA_TILE + voff);
                uint32_t b0[2], b1[2];
                b0[0] = tv[0]; b0[1] = tv[1];
                b1[0] = tv[2]; b1[1] = tv[3];
                mma_f16(oacc[nt * 2],     pf[j], b0);
                mma_f16(oacc[nt * 2 + 1], pf[j], b1);
            }
        }

        __syncthreads();
        if (kt + 2 < n_kt) {
            fa_issue_stage(sb, s, (kt + 2) * FAK, tid, kp, vp);
        } else {
            cp_commit();
        }
    }

    const float inv0 = 1.f / l0;
    const float inv1 = 1.f / l1;
#pragma unroll
    for (int t = 0; t < 16; t++) {
        const int col = t * 8 + lcolb;
        const size_t off0 = (size_t)lrow0 * D_MODEL + col;
        const size_t off1 = (size_t)(lrow0 + 8) * D_MODEL + col;
        ushort2 a, bq;
        a.x = __half_as_ushort(__float2half_rn(oacc[t][0] * inv0));
        a.y = __half_as_ushort(__float2half_rn(oacc[t][1] * inv0));
        bq.x = __half_as_ushort(__float2half_rn(oacc[t][2] * inv1));
        bq.y = __half_as_ushort(__float2half_rn(oacc[t][3] * inv1));
        ((ushort2*)oph)[off0 >> 1] = a;
        ((ushort2*)oph)[off1 >> 1] = bq;
    }
}

// ======================= host side =======================
extern "C" void kernel_launch(void* const* d_in, const int* in_sizes, int n_in,
                              void* d_out, int out_size) {
    const float* x  = (const float*)d_in[0];
    const float* wq = (const float*)d_in[1];
    const float* wk = (const float*)d_in[2];
    const float* wv = (const float*)d_in[3];
    const float* wo = (const float*)d_in[4];
    float* out = (float*)d_out;

    __half *x16, *o16, *wo16;
    cudaGetSymbolAddress((void**)&x16, g_x16);
    cudaGetSymbolAddress((void**)&o16, g_o16);
    cudaGetSymbolAddress((void**)&wo16, g_wo16);

    rope_table_kernel<<<(S_LEN * (HD / 2) + 255) / 256, 256>>>();

    const int total4 = XN4 + 4 * WN4;
    cvt_all_kernel<<<(total4 + 255) / 256, 256>>>(x, wq, wk, wv, wo);

    cudaFuncSetAttribute(gemm_qkv, cudaFuncAttributeMaxDynamicSharedMemorySize, GEMM_SMEM);
    cudaFuncSetAttribute(gemm_out, cudaFuncAttributeMaxDynamicSharedMemorySize, GEMM_SMEM);

    gemm_qkv<<<dim3(48, MROWS / GBM), 256, GEMM_SMEM>>>(x16);

    cudaFuncSetAttribute(flash_attn_mma, cudaFuncAttributeMaxDynamicSharedMemorySize, FA_SMEM);
    flash_attn_mma<<<dim3(S_LEN / FAQ, B_SZ * NH), 128, FA_SMEM>>>();

    gemm_out<<<dim3(16, MROWS / GBM), 256, GEMM_SMEM>>>(o16, wo16, out);
}

// round 16
// speedup vs baseline: 1.1161x; 1.0362x over previous
#include <cuda_runtime.h>
#include <cuda_fp16.h>
#include <stdint.h>
#include <math.h>

#define S_LEN 2048
#define B_SZ 2
#define D_MODEL 2048
#define NH 16
#define HD 128
#define MROWS (B_SZ * S_LEN)
#define KDIM 2048

// ---------------- scratch (static device allocations: allowed) ----------------
__device__ float g_cos[S_LEN * (HD / 2)];
__device__ float g_sin[S_LEN * (HD / 2)];

__device__ __half g_x16[(size_t)MROWS * D_MODEL];
__device__ __half g_o16[(size_t)MROWS * D_MODEL];
__device__ __half g_wq16[(size_t)D_MODEL * D_MODEL];
__device__ __half g_wk16[(size_t)D_MODEL * D_MODEL];
__device__ __half g_wv16[(size_t)D_MODEL * D_MODEL];
__device__ __half g_wo16[(size_t)D_MODEL * D_MODEL];

// fp16 attention operands (written by QKV GEMM epilogue, rope applied)
__device__ __half g_qh2a[(size_t)MROWS * D_MODEL];   // q hi
__device__ __half g_ql2a[(size_t)MROWS * D_MODEL];   // q lo
__device__ __half g_k16[(size_t)MROWS * D_MODEL];    // k
__device__ __half g_v16[(size_t)MROWS * D_MODEL];    // v

// ======================= low-level helpers ====================================
__device__ __forceinline__ uint32_t smem_u32(const void* p) {
    uint32_t a;
    asm("{ .reg .u64 t; cvta.to.shared.u64 t, %1; cvt.u32.u64 %0, t; }" : "=r"(a) : "l"(p));
    return a;
}
__device__ __forceinline__ void cp16(uint32_t dst, const void* src) {
    asm volatile("cp.async.cg.shared.global [%0], [%1], 16;" :: "r"(dst), "l"(src));
}
__device__ __forceinline__ void cp_commit() {
    asm volatile("cp.async.commit_group;" ::: "memory");
}
#define CP_WAIT(n) asm volatile("cp.async.wait_group " #n ";" ::: "memory")

__device__ __forceinline__ void ldsm_x4(uint32_t* r, uint32_t addr) {
    asm volatile("ldmatrix.sync.aligned.m8n8.x4.shared.b16 {%0,%1,%2,%3}, [%4];"
                 : "=r"(r[0]), "=r"(r[1]), "=r"(r[2]), "=r"(r[3]) : "r"(addr));
}
__device__ __forceinline__ void ldsm_x4_t(uint32_t* r, uint32_t addr) {
    asm volatile("ldmatrix.sync.aligned.m8n8.x4.trans.shared.b16 {%0,%1,%2,%3}, [%4];"
                 : "=r"(r[0]), "=r"(r[1]), "=r"(r[2]), "=r"(r[3]) : "r"(addr));
}
__device__ __forceinline__ void mma_f16(float* d, const uint32_t* a, const uint32_t* b) {
    asm volatile(
        "mma.sync.aligned.m16n8k16.row.col.f32.f16.f16.f32 "
        "{%0,%1,%2,%3}, {%4,%5,%6,%7}, {%8,%9}, {%0,%1,%2,%3};"
        : "+f"(d[0]), "+f"(d[1]), "+f"(d[2]), "+f"(d[3])
        : "r"(a[0]), "r"(a[1]), "r"(a[2]), "r"(a[3]), "r"(b[0]), "r"(b[1]));
}

#define SWZ(x) ((x) ^ (((x) >> 3) & 0x70))
#define SWZ256(x) ((x) ^ (((x) >> 4) & 0x70))

// =========== fp16 1-pass GEMM: 256 thr, warp 64x32, 3-stage ==================
#define GBM 128
#define GBN 128
#define NCHUNK (KDIM / 64)
#define TILE_B (GBM * 128)
#define STAGE_B (2 * TILE_B)      // A, B tiles = 32KB
#define NSTAGE 3
#define GEMM_SMEM (NSTAGE * STAGE_B)   // 98304; 2 CTAs/SM (regs pinned <=128)

__device__ __forceinline__ void gemm_issue1(
    const __half* Ah, const __half* Bh,
    uint32_t sb0, int m0, int n0, int tid, int c, int s)
{
    const uint32_t st = sb0 + (uint32_t)s * STAGE_B;
    const size_t kb = (size_t)c * 128;
    const int lq = tid & 7;
#pragma unroll
    for (int i = 0; i < 4; i++) {
        const int r = (tid + i * 256) >> 3;
        const uint32_t dsw = SWZ((uint32_t)(r * 128 + lq * 16));
        const size_t arow = (size_t)(m0 + r) * (KDIM * 2) + kb + (size_t)lq * 16;
        const size_t brow = (size_t)(n0 + r) * (KDIM * 2) + kb + (size_t)lq * 16;
        cp16(st + dsw,          (const char*)Ah + arow);
        cp16(st + TILE_B + dsw, (const char*)Bh + brow);
    }
    cp_commit();
}

__device__ __forceinline__ void gemm_core(
    float acc[4][4][4],
    const __half* Ah, const __half* Bh,
    uint32_t sb0, int m0, int n0)
{
    const int tid = threadIdx.x;
    const int wid = tid >> 5;
    const int lane = tid & 31;
    const int m_base = (wid >> 2) * 64;
    const int n_base = (wid & 3) * 32;

#pragma unroll
    for (int i = 0; i < 4; i++) {
#pragma unroll
        for (int j = 0; j < 4; j++) {
#pragma unroll
            for (int e = 0; e < 4; e++) { acc[i][j][e] = 0.f; }
        }
    }

    gemm_issue1(Ah, Bh, sb0, m0, n0, tid, 0, 0);
    gemm_issue1(Ah, Bh, sb0, m0, n0, tid, 1, 1);
    gemm_issue1(Ah, Bh, sb0, m0, n0, tid, 2, 2);

    const int g8 = lane >> 3;
    const int r8 = lane & 7;
    const int rowoff = (g8 & 1) * 8 + r8;
    const int qhi = g8 >> 1;

    int s = 0;
    for (int c = 0; c < NCHUNK; c++) {
        CP_WAIT(2);
        __syncthreads();
        const uint32_t sA = sb0 + (uint32_t)s * STAGE_B;
        const uint32_t sB = sA + TILE_B;

#pragma unroll
        for (int ks = 0; ks < 4; ks++) {
            const int quad = ks * 2 + qhi;
            uint32_t ah[4][4], bh[4][2];
#pragma unroll
            for (int mi = 0; mi < 4; mi++) {
                const uint32_t off = SWZ((uint32_t)((m_base + mi * 16 + rowoff) * 128 + quad * 16));
                ldsm_x4(ah[mi], sA + off);
            }
#pragma unroll
            for (int p = 0; p < 2; p++) {
                const uint32_t off = SWZ((uint32_t)((n_base + p * 16 + rowoff) * 128 + quad * 16));
                uint32_t t[4];
                ldsm_x4(t, sB + off);
                bh[2 * p][0] = t[0]; bh[2 * p][1] = t[2];
                bh[2 * p + 1][0] = t[1]; bh[2 * p + 1][1] = t[3];
            }
#pragma unroll
            for (int mi = 0; mi < 4; mi++) {
#pragma unroll
                for (int ni = 0; ni < 4; ni++) {
                    mma_f16(acc[mi][ni], ah[mi], bh[ni]);
                }
            }
        }
        __syncthreads();
        if (c + NSTAGE < NCHUNK) {
            gemm_issue1(Ah, Bh, sb0, m0, n0, tid, c + NSTAGE, s);
        } else {
            cp_commit();
        }
        s = (s == NSTAGE - 1) ? 0 : (s + 1);
    }
}

// ---- fused QKV projection: epilogue applies RoPE (q,k) + fp16 rounding ------
__global__ __launch_bounds__(256, 2) void gemm_qkv(const __half* __restrict__ Ah)
{
    extern __shared__ char smem[];
    const uint32_t sb0 = smem_u32(smem);

    const int nb = blockIdx.x;
    const int which = nb >> 4;               // 0=q, 1=k, 2=v
    const int n0 = (nb & 15) * GBN;
    const __half* Bh = (which == 0) ? g_wq16 : ((which == 1) ? g_wk16 : g_wv16);
    const int m0 = blockIdx.y * GBM;

    float acc[4][4][4];
    gemm_core(acc, Ah, Bh, sb0, m0, n0);

    const int wid = threadIdx.x >> 5;
    const int lane = threadIdx.x & 31;
    const int m_base = (wid >> 2) * 64;
    const int n_base = (wid & 3) * 32;
    const int erow = lane >> 2;
    const int ecol = (lane & 3) * 2;

#pragma unroll
    for (int mi = 0; mi < 4; mi++) {
#pragma unroll
        for (int ni = 0; ni < 4; ni++) {
            const int row = m0 + m_base + mi * 16 + erow;
            const int col = n0 + n_base + ni * 8 + ecol;     // even
            float a0 = acc[mi][ni][0], a1 = acc[mi][ni][1];
            float b0 = acc[mi][ni][2], b1 = acc[mi][ni][3];
            if (which < 2) {    // RoPE on q, k
                const int i = (col & 127) >> 1;
                const int s1 = row & (S_LEN - 1);
                const int s2 = (row + 8) & (S_LEN - 1);
                float c1 = g_cos[(s1 << 6) + i], sn1 = g_sin[(s1 << 6) + i];
                float c2 = g_cos[(s2 << 6) + i], sn2 = g_sin[(s2 << 6) + i];
                float t0 = a0 * c1 - a1 * sn1;
                float t1 = a0 * sn1 + a1 * c1;
                a0 = t0; a1 = t1;
                t0 = b0 * c2 - b1 * sn2;
                t1 = b0 * sn2 + b1 * c2;
                b0 = t0; b1 = t1;
            }
            const size_t off0 = (size_t)row * D_MODEL + col;
            const size_t off1 = (size_t)(row + 8) * D_MODEL + col;
            __half ha0 = __float2half_rn(a0);
            __half ha1 = __float2half_rn(a1);
            __half hb0 = __float2half_rn(b0);
            __half hb1 = __float2half_rn(b1);
            ushort2 va, vb;
            va.x = __half_as_ushort(ha0); va.y = __half_as_ushort(ha1);
            vb.x = __half_as_ushort(hb0); vb.y = __half_as_ushort(hb1);
            if (which == 0) {
                ((ushort2*)g_qh2a)[off0 >> 1] = va;
                ((ushort2*)g_qh2a)[off1 >> 1] = vb;
                __half la0 = __float2half_rn(a0 - __half2float(ha0));
                __half la1 = __float2half_rn(a1 - __half2float(ha1));
                __half lb0 = __float2half_rn(b0 - __half2float(hb0));
                __half lb1 = __float2half_rn(b1 - __half2float(hb1));
                ushort2 wa, wb;
                wa.x = __half_as_ushort(la0); wa.y = __half_as_ushort(la1);
                wb.x = __half_as_ushort(lb0); wb.y = __half_as_ushort(lb1);
                ((ushort2*)g_ql2a)[off0 >> 1] = wa;
                ((ushort2*)g_ql2a)[off1 >> 1] = wb;
            } else if (which == 1) {
                ((ushort2*)g_k16)[off0 >> 1] = va;
                ((ushort2*)g_k16)[off1 >> 1] = vb;
            } else {
                ((ushort2*)g_v16)[off0 >> 1] = va;
                ((ushort2*)g_v16)[off1 >> 1] = vb;
            }
        }
    }
}

// ---- output projection: fp32 epilogue to d_out ------------------------------
__global__ __launch_bounds__(256, 2) void gemm_out(
    const __half* __restrict__ Ah,
    const __half* __restrict__ Bh, float* __restrict__ C)
{
    extern __shared__ char smem[];
    const uint32_t sb0 = smem_u32(smem);
    const int n0 = blockIdx.x * GBN;
    const int m0 = blockIdx.y * GBM;

    float acc[4][4][4];
    gemm_core(acc, Ah, Bh, sb0, m0, n0);

    const int wid = threadIdx.x >> 5;
    const int lane = threadIdx.x & 31;
    const int m_base = (wid >> 2) * 64;
    const int n_base = (wid & 3) * 32;
    const int erow = lane >> 2;
    const int ecol = (lane & 3) * 2;
#pragma unroll
    for (int mi = 0; mi < 4; mi++) {
#pragma unroll
        for (int ni = 0; ni < 4; ni++) {
            const int row = m0 + m_base + mi * 16 + erow;
            const int col = n0 + n_base + ni * 8 + ecol;
            *(float2*)(C + (size_t)row * D_MODEL + col) =
                make_float2(acc[mi][ni][0], acc[mi][ni][1]);
            *(float2*)(C + (size_t)(row + 8) * D_MODEL + col) =
                make_float2(acc[mi][ni][2], acc[mi][ni][3]);
        }
    }
}

// ---------------- fused fp32 -> fp16 convert (x + 4 weights) ----------------
#define XN4 (MROWS * D_MODEL / 4)
#define WN4 (D_MODEL * D_MODEL / 4)

__global__ void cvt_all_kernel(const float* __restrict__ x,
                               const float* __restrict__ wq,
                               const float* __restrict__ wk,
                               const float* __restrict__ wv,
                               const float* __restrict__ wo)
{
    int i = blockIdx.x * blockDim.x + threadIdx.x;
    const float* src;
    __half* dst;
    int j = i;
    if (j < XN4) { src = x; dst = g_x16; }
    else {
        j -= XN4;
        if (j < WN4) { src = wq; dst = g_wq16; }
        else {
            j -= WN4;
            if (j < WN4) { src = wk; dst = g_wk16; }
            else {
                j -= WN4;
                if (j < WN4) { src = wv; dst = g_wv16; }
                else {
                    j -= WN4;
                    if (j >= WN4) return;
                    src = wo; dst = g_wo16;
                }
            }
        }
    }
    float4 f = ((const float4*)src)[j];
    ushort4 hv;
    hv.x = __half_as_ushort(__float2half_rn(f.x));
    hv.y = __half_as_ushort(__float2half_rn(f.y));
    hv.z = __half_as_ushort(__float2half_rn(f.z));
    hv.w = __half_as_ushort(__float2half_rn(f.w));
    ((ushort4*)dst)[j] = hv;
}

// ---------------- RoPE table (double precision angles) ----------------
__global__ void rope_table_kernel() {
    int idx = blockIdx.x * blockDim.x + threadIdx.x;
    if (idx >= S_LEN * (HD / 2)) return;
    int s = idx >> 6;
    int i = idx & 63;
    double freq = exp(-log(10000.0) * (double)(2 * i) / (double)HD);
    double ang = (double)s * freq;
    g_cos[idx] = (float)cos(ang);
    g_sin[idx] = (float)sin(ang);
}

// ========= Flash attention (causal) fp16: QK 2-pass, PV 1-pass, FAK=64 =======
#define FAQ 64
#define FAK 64
#define FA_QHI 0
#define FA_QLO 16384
#define FA_STG 32768
#define FA_TILE 16384                 // K or V tile: 64 rows x 256B
#define FA_STAGE (2 * FA_TILE)        // 32KB
#define FA_SMEM (FA_STG + 2 * FA_STAGE)   // 98304 -> 2 CTAs/SM

__device__ __forceinline__ void fa_issue_stage(
    uint32_t sb, int s, int k0, int tid,
    const __half* kp, const __half* vp)
{
    const uint32_t st = sb + FA_STG + (uint32_t)s * FA_STAGE;
#pragma unroll
    for (int i = 0; i < 8; i++) {
        int idx = i * 128 + tid;
        int row = idx >> 4, ch = idx & 15;
        uint32_t dsw = SWZ256((uint32_t)(row * 256 + ch * 16));
        const char* srck = (const char*)kp + (size_t)(k0 + row) * (D_MODEL * 2) + (size_t)ch * 16;
        const char* srcv = (const char*)vp + (size_t)(k0 + row) * (D_MODEL * 2) + (size_t)ch * 16;
        cp16(st + dsw,           srck);
        cp16(st + FA_TILE + dsw, srcv);
    }
    cp_commit();
}

__global__ __launch_bounds__(128, 2) void flash_attn_mma() {
    extern __shared__ char smraw[];
    const uint32_t sb = smem_u32(smraw);
    const int tid = threadIdx.x;
    const int lane = tid & 31;
    const int w = tid >> 5;
    const int qt = (int)gridDim.x - 1 - (int)blockIdx.x;   // heavy tiles first
    const int bh = blockIdx.y;
    const int b = bh >> 4, h = bh & 15;
    const int q0 = qt * FAQ;
    const int n_kt = qt + 1;

    const size_t base = (size_t)b * S_LEN * D_MODEL + (size_t)h * HD;
    const __half* qhp = g_qh2a + base;
    const __half* qlp = g_ql2a + base;
    const __half* kp  = g_k16 + base;
    const __half* vp  = g_v16 + base;
    __half* oph = g_o16 + base;

#pragma unroll
    for (int i = 0; i < 8; i++) {
        int idx = i * 128 + tid;
        int row = idx >> 4, ch = idx & 15;
        uint32_t dsw = SWZ256((uint32_t)(row * 256 + ch * 16));
        const char* srch = (const char*)qhp + (size_t)(q0 + row) * (D_MODEL * 2) + (size_t)ch * 16;
        const char* srcl = (const char*)qlp + (size_t)(q0 + row) * (D_MODEL * 2) + (size_t)ch * 16;
        cp16(sb + FA_QHI + dsw, srch);
        cp16(sb + FA_QLO + dsw, srcl);
    }
    cp_commit();
    fa_issue_stage(sb, 0, 0, tid, kp, vp);
    // stage 1 prefetch (reads rows 64..127 even when n_kt==1: in-bounds, unused)
    fa_issue_stage(sb, 1, FAK < S_LEN ? FAK : 0, tid, kp, vp);

    const int g8 = lane >> 3;
    const int r8 = lane & 7;
    const int rowoff = (g8 & 1) * 8 + r8;
    const int qsel = g8 >> 1;

    float oacc[16][4];
#pragma unroll
    for (int t = 0; t < 16; t++) {
#pragma unroll
        for (int e = 0; e < 4; e++) { oacc[t][e] = 0.f; }
    }
    float m0 = -1e30f, m1 = -1e30f, l0 = 0.f, l1 = 0.f;
    const float sm_scale = 0.08838834764831843f;

    const int lrow0 = q0 + w * 16 + (lane >> 2);
    const int lcolb = (lane & 3) * 2;

    for (int kt = 0; kt < n_kt; kt++) {
        const int s = kt & 1;
        const int k0 = kt * FAK;
        CP_WAIT(1);
        __syncthreads();
        const uint32_t stg = sb + FA_STG + (uint32_t)s * FA_STAGE;

        // ---- S[16][64] = Q @ K^T : 2-pass (Qh + Ql) x Kf16 ----
        float sacc[8][4];
#pragma unroll
        for (int t = 0; t < 8; t++) {
#pragma unroll
            for (int e = 0; e < 4; e++) { sacc[t][e] = 0.f; }
        }
#pragma unroll
        for (int ks = 0; ks < 8; ks++) {
            const int quad = ks * 2 + qsel;
            uint32_t qfh[4], qfl[4];
            const uint32_t qoff = SWZ256((uint32_t)((w * 16 + rowoff) * 256 + quad * 16));
            ldsm_x4(qfh, sb + FA_QHI + qoff);
            ldsm_x4(qfl, sb + FA_QLO + qoff);
#pragma unroll
            for (int nt = 0; nt < 4; nt++) {
                const uint32_t koff = SWZ256((uint32_t)((nt * 16 + rowoff) * 256 + quad * 16));
                uint32_t tk[4];
                ldsm_x4(tk, stg + koff);
                uint32_t b0[2], b1[2];
                b0[0] = tk[0]; b0[1] = tk[2];
                b1[0] = tk[1]; b1[1] = tk[3];
                mma_f16(sacc[nt * 2],     qfh, b0);
                mma_f16(sacc[nt * 2],     qfl, b0);
                mma_f16(sacc[nt * 2 + 1], qfh, b1);
                mma_f16(sacc[nt * 2 + 1], qfl, b1);
            }
        }

        // ---- scale + causal mask ----
        const int need_mask = (k0 + FAK - 1 > q0 + w * 16) ? 1 : 0;
#pragma unroll
        for (int t = 0; t < 8; t++) {
#pragma unroll
            for (int e = 0; e < 4; e++) {
                float sv = sacc[t][e] * sm_scale;
                if (need_mask) {
                    int col = k0 + t * 8 + lcolb + (e & 1);
                    int row = lrow0 + ((e >> 1) & 1) * 8;
                    if (col > row) { sv = -1e30f; }
                }
                sacc[t][e] = sv;
            }
        }

        // ---- online softmax ----
        float rm0 = sacc[0][0], rm1 = sacc[0][2];
#pragma unroll
        for (int t = 0; t < 8; t++) {
            rm0 = fmaxf(rm0, fmaxf(sacc[t][0], sacc[t][1]));
            rm1 = fmaxf(rm1, fmaxf(sacc[t][2], sacc[t][3]));
        }
        rm0 = fmaxf(rm0, __shfl_xor_sync(0xffffffffu, rm0, 1));
        rm0 = fmaxf(rm0, __shfl_xor_sync(0xffffffffu, rm0, 2));
        rm1 = fmaxf(rm1, __shfl_xor_sync(0xffffffffu, rm1, 1));
        rm1 = fmaxf(rm1, __shfl_xor_sync(0xffffffffu, rm1, 2));
        float mn0 = fmaxf(m0, rm0);
        float mn1 = fmaxf(m1, rm1);
        float alpha0 = __expf(m0 - mn0);
        float alpha1 = __expf(m1 - mn1);
        float rs0 = 0.f, rs1 = 0.f;
#pragma unroll
        for (int t = 0; t < 8; t++) {
            float p0 = __expf(sacc[t][0] - mn0);
            float p1 = __expf(sacc[t][1] - mn0);
            float p2 = __expf(sacc[t][2] - mn1);
            float p3 = __expf(sacc[t][3] - mn1);
            rs0 += p0 + p1;
            rs1 += p2 + p3;
            sacc[t][0] = p0; sacc[t][1] = p1;
            sacc[t][2] = p2; sacc[t][3] = p3;
        }
        rs0 += __shfl_xor_sync(0xffffffffu, rs0, 1);
        rs0 += __shfl_xor_sync(0xffffffffu, rs0, 2);
        rs1 += __shfl_xor_sync(0xffffffffu, rs1, 1);
        rs1 += __shfl_xor_sync(0xffffffffu, rs1, 2);
        l0 = l0 * alpha0 + rs0;
        l1 = l1 * alpha1 + rs1;
        m0 = mn0; m1 = mn1;
#pragma unroll
        for (int t = 0; t < 16; t++) {
            oacc[t][0] *= alpha0; oacc[t][1] *= alpha0;
            oacc[t][2] *= alpha1; oacc[t][3] *= alpha1;
        }

        // ---- pack P[16][64] to fp16 A-frags (4 k-subtiles of 16) ----
        uint32_t pf[4][4];
#pragma unroll
        for (int j = 0; j < 4; j++) {
#pragma unroll
            for (int idx = 0; idx < 4; idx++) {
                int st = 2 * j + (idx >> 1);
                int rp = (idx & 1) * 2;
                __half p0 = __float2half_rn(sacc[st][rp]);
                __half p1 = __float2half_rn(sacc[st][rp + 1]);
                pf[j][idx] = (uint32_t)__half_as_ushort(p0)
                           | ((uint32_t)__half_as_ushort(p1) << 16);
            }
        }

        // ---- O += P @ V : single pass fp16, V 64 rows ----
        const int vrow_base = (lane & 7) + ((lane >> 3) & 1) * 8;
        const int vcol_base = ((lane >> 4) & 1) * 16;
#pragma unroll
        for (int j = 0; j < 4; j++) {
#pragma unroll
            for (int nt = 0; nt < 8; nt++) {
                const int vr = j * 16 + vrow_base;
                const int vcb = nt * 32 + vcol_base;
                const uint32_t voff = SWZ256((uint32_t)(vr * 256 + vcb));
                uint32_t tv[4];
                ldsm_x4_t(tv, stg + FA_TILE + voff);
                uint32_t b0[2], b1[2];
                b0[0] = tv[0]; b0[1] = tv[1];
                b1[0] = tv[2]; b1[1] = tv[3];
                mma_f16(oacc[nt * 2],     pf[j], b0);
                mma_f16(oacc[nt * 2 + 1], pf[j], b1);
            }
        }

        __syncthreads();
        if (kt + 2 < n_kt) {
            fa_issue_stage(sb, s, (kt + 2) * FAK, tid, kp, vp);
        } else {
            cp_commit();
        }
    }

    // ---- epilogue: normalize, store fp16 o ----
    const float inv0 = 1.f / l0;
    const float inv1 = 1.f / l1;
#pragma unroll
    for (int t = 0; t < 16; t++) {
        const int col = t * 8 + lcolb;
        const size_t off0 = (size_t)lrow0 * D_MODEL + col;
        const size_t off1 = (size_t)(lrow0 + 8) * D_MODEL + col;
        ushort2 a, bq;
        a.x = __half_as_ushort(__float2half_rn(oacc[t][0] * inv0));
        a.y = __half_as_ushort(__float2half_rn(oacc[t][1] * inv0));
        bq.x = __half_as_ushort(__float2half_rn(oacc[t][2] * inv1));
        bq.y = __half_as_ushort(__float2half_rn(oacc[t][3] * inv1));
        ((ushort2*)oph)[off0 >> 1] = a;
        ((ushort2*)oph)[off1 >> 1] = bq;
    }
}

// ======================= host side =======================
extern "C" void kernel_launch(void* const* d_in, const int* in_sizes, int n_in,
                              void* d_out, int out_size) {
    const float* x  = (const float*)d_in[0];
    const float* wq = (const float*)d_in[1];
    const float* wk = (const float*)d_in[2];
    const float* wv = (const float*)d_in[3];
    const float* wo = (const float*)d_in[4];
    float* out = (float*)d_out;

    __half *x16, *o16, *wo16;
    cudaGetSymbolAddress((void**)&x16, g_x16);
    cudaGetSymbolAddress((void**)&o16, g_o16);
    cudaGetSymbolAddress((void**)&wo16, g_wo16);

    rope_table_kernel<<<(S_LEN * (HD / 2) + 255) / 256, 256>>>();

    const int total4 = XN4 + 4 * WN4;
    cvt_all_kernel<<<(total4 + 255) / 256, 256>>>(x, wq, wk, wv, wo);

    cudaFuncSetAttribute(gemm_qkv, cudaFuncAttributeMaxDynamicSharedMemorySize, GEMM_SMEM);
    cudaFuncSetAttribute(gemm_out, cudaFuncAttributeMaxDynamicSharedMemorySize, GEMM_SMEM);

    gemm_qkv<<<dim3(48, MROWS / GBM), 256, GEMM_SMEM>>>(x16);

    cudaFuncSetAttribute(flash_attn_mma, cudaFuncAttributeMaxDynamicSharedMemorySize, FA_SMEM);
    flash_attn_mma<<<dim3(S_LEN / FAQ, B_SZ * NH), 128, FA_SMEM>>>();

    gemm_out<<<dim3(16, MROWS / GBM), 256, GEMM_SMEM>>>(o16, wo16, out);
}

// round 17
// speedup vs baseline: 1.1843x; 1.0612x over previous
#include <cuda_runtime.h>
#include <cuda_fp16.h>
#include <stdint.h>
#include <math.h>

#define S_LEN 2048
#define B_SZ 2
#define D_MODEL 2048
#define NH 16
#define HD 128
#define MROWS (B_SZ * S_LEN)
#define KDIM 2048

// ---------------- scratch (static device allocations: allowed) ----------------
__device__ float g_cos[S_LEN * (HD / 2)];
__device__ float g_sin[S_LEN * (HD / 2)];

__device__ __half g_x16[(size_t)MROWS * D_MODEL];
__device__ __half g_o16[(size_t)MROWS * D_MODEL];
__device__ __half g_wq16[(size_t)D_MODEL * D_MODEL];
__device__ __half g_wk16[(size_t)D_MODEL * D_MODEL];
__device__ __half g_wv16[(size_t)D_MODEL * D_MODEL];
__device__ __half g_wo16[(size_t)D_MODEL * D_MODEL];

// fp16 attention operands (written by QKV GEMM epilogue, rope applied)
__device__ __half g_q16[(size_t)MROWS * D_MODEL];    // q (single fp16, roped)
__device__ __half g_k16[(size_t)MROWS * D_MODEL];    // k (single fp16, roped)
__device__ __half g_v16[(size_t)MROWS * D_MODEL];    // v

// ======================= low-level helpers ====================================
__device__ __forceinline__ uint32_t smem_u32(const void* p) {
    uint32_t a;
    asm("{ .reg .u64 t; cvta.to.shared.u64 t, %1; cvt.u32.u64 %0, t; }" : "=r"(a) : "l"(p));
    return a;
}
__device__ __forceinline__ void cp16(uint32_t dst, const void* src) {
    asm volatile("cp.async.cg.shared.global [%0], [%1], 16;" :: "r"(dst), "l"(src));
}
__device__ __forceinline__ void cp_commit() {
    asm volatile("cp.async.commit_group;" ::: "memory");
}
#define CP_WAIT(n) asm volatile("cp.async.wait_group " #n ";" ::: "memory")

__device__ __forceinline__ void ldsm_x4(uint32_t* r, uint32_t addr) {
    asm volatile("ldmatrix.sync.aligned.m8n8.x4.shared.b16 {%0,%1,%2,%3}, [%4];"
                 : "=r"(r[0]), "=r"(r[1]), "=r"(r[2]), "=r"(r[3]) : "r"(addr));
}
__device__ __forceinline__ void ldsm_x4_t(uint32_t* r, uint32_t addr) {
    asm volatile("ldmatrix.sync.aligned.m8n8.x4.trans.shared.b16 {%0,%1,%2,%3}, [%4];"
                 : "=r"(r[0]), "=r"(r[1]), "=r"(r[2]), "=r"(r[3]) : "r"(addr));
}
__device__ __forceinline__ void mma_f16(float* d, const uint32_t* a, const uint32_t* b) {
    asm volatile(
        "mma.sync.aligned.m16n8k16.row.col.f32.f16.f16.f32 "
        "{%0,%1,%2,%3}, {%4,%5,%6,%7}, {%8,%9}, {%0,%1,%2,%3};"
        : "+f"(d[0]), "+f"(d[1]), "+f"(d[2]), "+f"(d[3])
        : "r"(a[0]), "r"(a[1]), "r"(a[2]), "r"(a[3]), "r"(b[0]), "r"(b[1]));
}

#define SWZ(x) ((x) ^ (((x) >> 3) & 0x70))
#define SWZ256(x) ((x) ^ (((x) >> 4) & 0x70))

// =========== fp16 1-pass GEMM: 256 thr, warp 64x32, 3-stage ==================
#define GBM 128
#define GBN 128
#define NCHUNK (KDIM / 64)
#define TILE_B (GBM * 128)
#define STAGE_B (2 * TILE_B)
#define NSTAGE 3
#define GEMM_SMEM (NSTAGE * STAGE_B)   // 98304

__device__ __forceinline__ void gemm_issue1(
    const __half* Ah, const __half* Bh,
    uint32_t sb0, int m0, int n0, int tid, int c, int s)
{
    const uint32_t st = sb0 + (uint32_t)s * STAGE_B;
    const size_t kb = (size_t)c * 128;
    const int lq = tid & 7;
#pragma unroll
    for (int i = 0; i < 4; i++) {
        const int r = (tid + i * 256) >> 3;
        const uint32_t dsw = SWZ((uint32_t)(r * 128 + lq * 16));
        const size_t arow = (size_t)(m0 + r) * (KDIM * 2) + kb + (size_t)lq * 16;
        const size_t brow = (size_t)(n0 + r) * (KDIM * 2) + kb + (size_t)lq * 16;
        cp16(st + dsw,          (const char*)Ah + arow);
        cp16(st + TILE_B + dsw, (const char*)Bh + brow);
    }
    cp_commit();
}

__device__ __forceinline__ void gemm_core(
    float acc[4][4][4],
    const __half* Ah, const __half* Bh,
    uint32_t sb0, int m0, int n0)
{
    const int tid = threadIdx.x;
    const int wid = tid >> 5;
    const int lane = tid & 31;
    const int m_base = (wid >> 2) * 64;
    const int n_base = (wid & 3) * 32;

#pragma unroll
    for (int i = 0; i < 4; i++) {
#pragma unroll
        for (int j = 0; j < 4; j++) {
#pragma unroll
            for (int e = 0; e < 4; e++) { acc[i][j][e] = 0.f; }
        }
    }

    gemm_issue1(Ah, Bh, sb0, m0, n0, tid, 0, 0);
    gemm_issue1(Ah, Bh, sb0, m0, n0, tid, 1, 1);
    gemm_issue1(Ah, Bh, sb0, m0, n0, tid, 2, 2);

    const int g8 = lane >> 3;
    const int r8 = lane & 7;
    const int rowoff = (g8 & 1) * 8 + r8;
    const int qhi = g8 >> 1;

    int s = 0;
    for (int c = 0; c < NCHUNK; c++) {
        CP_WAIT(2);
        __syncthreads();
        const uint32_t sA = sb0 + (uint32_t)s * STAGE_B;
        const uint32_t sB = sA + TILE_B;

#pragma unroll
        for (int ks = 0; ks < 4; ks++) {
            const int quad = ks * 2 + qhi;
            uint32_t ah[4][4], bh[4][2];
#pragma unroll
            for (int mi = 0; mi < 4; mi++) {
                const uint32_t off = SWZ((uint32_t)((m_base + mi * 16 + rowoff) * 128 + quad * 16));
                ldsm_x4(ah[mi], sA + off);
            }
#pragma unroll
            for (int p = 0; p < 2; p++) {
                const uint32_t off = SWZ((uint32_t)((n_base + p * 16 + rowoff) * 128 + quad * 16));
                uint32_t t[4];
                ldsm_x4(t, sB + off);
                bh[2 * p][0] = t[0]; bh[2 * p][1] = t[2];
                bh[2 * p + 1][0] = t[1]; bh[2 * p + 1][1] = t[3];
            }
#pragma unroll
            for (int mi = 0; mi < 4; mi++) {
#pragma unroll
                for (int ni = 0; ni < 4; ni++) {
                    mma_f16(acc[mi][ni], ah[mi], bh[ni]);
                }
            }
        }
        __syncthreads();
        if (c + NSTAGE < NCHUNK) {
            gemm_issue1(Ah, Bh, sb0, m0, n0, tid, c + NSTAGE, s);
        } else {
            cp_commit();
        }
        s = (s == NSTAGE - 1) ? 0 : (s + 1);
    }
}

// ---- fused QKV projection: epilogue applies RoPE (q,k) + fp16 rounding ------
__global__ __launch_bounds__(256, 2) void gemm_qkv(const __half* __restrict__ Ah)
{
    extern __shared__ char smem[];
    const uint32_t sb0 = smem_u32(smem);

    const int nb = blockIdx.x;
    const int which = nb >> 4;               // 0=q, 1=k, 2=v
    const int n0 = (nb & 15) * GBN;
    const __half* Bh = (which == 0) ? g_wq16 : ((which == 1) ? g_wk16 : g_wv16);
    __half* dst = (which == 0) ? g_q16 : ((which == 1) ? g_k16 : g_v16);
    const int m0 = blockIdx.y * GBM;

    float acc[4][4][4];
    gemm_core(acc, Ah, Bh, sb0, m0, n0);

    const int wid = threadIdx.x >> 5;
    const int lane = threadIdx.x & 31;
    const int m_base = (wid >> 2) * 64;
    const int n_base = (wid & 3) * 32;
    const int erow = lane >> 2;
    const int ecol = (lane & 3) * 2;

#pragma unroll
    for (int mi = 0; mi < 4; mi++) {
#pragma unroll
        for (int ni = 0; ni < 4; ni++) {
            const int row = m0 + m_base + mi * 16 + erow;
            const int col = n0 + n_base + ni * 8 + ecol;     // even
            float a0 = acc[mi][ni][0], a1 = acc[mi][ni][1];
            float b0 = acc[mi][ni][2], b1 = acc[mi][ni][3];
            if (which < 2) {    // RoPE on q, k
                const int i = (col & 127) >> 1;
                const int s1 = row & (S_LEN - 1);
                const int s2 = (row + 8) & (S_LEN - 1);
                float c1 = g_cos[(s1 << 6) + i], sn1 = g_sin[(s1 << 6) + i];
                float c2 = g_cos[(s2 << 6) + i], sn2 = g_sin[(s2 << 6) + i];
                float t0 = a0 * c1 - a1 * sn1;
                float t1 = a0 * sn1 + a1 * c1;
                a0 = t0; a1 = t1;
                t0 = b0 * c2 - b1 * sn2;
                t1 = b0 * sn2 + b1 * c2;
                b0 = t0; b1 = t1;
            }
            const size_t off0 = (size_t)row * D_MODEL + col;
            const size_t off1 = (size_t)(row + 8) * D_MODEL + col;
            ushort2 va, vb;
            va.x = __half_as_ushort(__float2half_rn(a0));
            va.y = __half_as_ushort(__float2half_rn(a1));
            vb.x = __half_as_ushort(__float2half_rn(b0));
            vb.y = __half_as_ushort(__float2half_rn(b1));
            ((ushort2*)dst)[off0 >> 1] = va;
            ((ushort2*)dst)[off1 >> 1] = vb;
        }
    }
}

// ---- output projection: fp32 epilogue to d_out ------------------------------
__global__ __launch_bounds__(256, 2) void gemm_out(
    const __half* __restrict__ Ah,
    const __half* __restrict__ Bh, float* __restrict__ C)
{
    extern __shared__ char smem[];
    const uint32_t sb0 = smem_u32(smem);
    const int n0 = blockIdx.x * GBN;
    const int m0 = blockIdx.y * GBM;

    float acc[4][4][4];
    gemm_core(acc, Ah, Bh, sb0, m0, n0);

    const int wid = threadIdx.x >> 5;
    const int lane = threadIdx.x & 31;
    const int m_base = (wid >> 2) * 64;
    const int n_base = (wid & 3) * 32;
    const int erow = lane >> 2;
    const int ecol = (lane & 3) * 2;
#pragma unroll
    for (int mi = 0; mi < 4; mi++) {
#pragma unroll
        for (int ni = 0; ni < 4; ni++) {
            const int row = m0 + m_base + mi * 16 + erow;
            const int col = n0 + n_base + ni * 8 + ecol;
            *(float2*)(C + (size_t)row * D_MODEL + col) =
                make_float2(acc[mi][ni][0], acc[mi][ni][1]);
            *(float2*)(C + (size_t)(row + 8) * D_MODEL + col) =
                make_float2(acc[mi][ni][2], acc[mi][ni][3]);
        }
    }
}

// ---------------- fused fp32 -> fp16 convert, 4 float4 per thread ------------
#define XN4 (MROWS * D_MODEL / 4)
#define WN4 (D_MODEL * D_MODEL / 4)
#define CVT_TOTAL4 (XN4 + 4 * WN4)

__global__ void cvt_all_kernel(const float* __restrict__ x,
                               const float* __restrict__ wq,
                               const float* __restrict__ wk,
                               const float* __restrict__ wv,
                               const float* __restrict__ wo)
{
#pragma unroll
    for (int it = 0; it < 4; it++) {
        int i = (blockIdx.x * 4 + it) * blockDim.x + threadIdx.x;
        if (i >= CVT_TOTAL4) continue;
        const float* src;
        __half* dst;
        int j = i;
        if (j < XN4) { src = x; dst = g_x16; }
        else {
            j -= XN4;
            if (j < WN4) { src = wq; dst = g_wq16; }
            else {
                j -= WN4;
                if (j < WN4) { src = wk; dst = g_wk16; }
                else {
                    j -= WN4;
                    if (j < WN4) { src = wv; dst = g_wv16; }
                    else { j -= WN4; src = wo; dst = g_wo16; }
                }
            }
        }
        float4 f = ((const float4*)src)[j];
        ushort4 hv;
        hv.x = __half_as_ushort(__float2half_rn(f.x));
        hv.y = __half_as_ushort(__float2half_rn(f.y));
        hv.z = __half_as_ushort(__float2half_rn(f.z));
        hv.w = __half_as_ushort(__float2half_rn(f.w));
        ((ushort4*)dst)[j] = hv;
    }
}

// ---------------- RoPE table (double precision angles) ----------------
__global__ void rope_table_kernel() {
    int idx = blockIdx.x * blockDim.x + threadIdx.x;
    if (idx >= S_LEN * (HD / 2)) return;
    int s = idx >> 6;
    int i = idx & 63;
    double freq = exp(-log(10000.0) * (double)(2 * i) / (double)HD);
    double ang = (double)s * freq;
    g_cos[idx] = (float)cos(ang);
    g_sin[idx] = (float)sin(ang);
}

// ==== Flash attention (causal) fp16: QK 1-pass, PV 1-pass, FAK=64, Q in regs ==
#define FAQ 64
#define FAK 64
#define FA_Q 0
#define FA_STG 16384
#define FA_TILE 16384                 // K or V tile: 64 rows x 256B
#define FA_STAGE (2 * FA_TILE)        // 32KB
#define FA_SMEM (FA_STG + 2 * FA_STAGE)   // 81920

__device__ __forceinline__ void fa_issue_stage(
    uint32_t sb, int s, int k0, int tid,
    const __half* kp, const __half* vp)
{
    const uint32_t st = sb + FA_STG + (uint32_t)s * FA_STAGE;
#pragma unroll
    for (int i = 0; i < 8; i++) {
        int idx = i * 128 + tid;
        int row = idx >> 4, ch = idx & 15;
        uint32_t dsw = SWZ256((uint32_t)(row * 256 + ch * 16));
        const char* srck = (const char*)kp + (size_t)(k0 + row) * (D_MODEL * 2) + (size_t)ch * 16;
        const char* srcv = (const char*)vp + (size_t)(k0 + row) * (D_MODEL * 2) + (size_t)ch * 16;
        cp16(st + dsw,           srck);
        cp16(st + FA_TILE + dsw, srcv);
    }
    cp_commit();
}

__global__ __launch_bounds__(128, 2) void flash_attn_mma() {
    extern __shared__ char smraw[];
    const uint32_t sb = smem_u32(smraw);
    const int tid = threadIdx.x;
    const int lane = tid & 31;
    const int w = tid >> 5;
    const int qt = (int)gridDim.x - 1 - (int)blockIdx.x;   // heavy tiles first
    const int bh = blockIdx.y;
    const int b = bh >> 4, h = bh & 15;
    const int q0 = qt * FAQ;
    const int n_kt = qt + 1;

    const size_t base = (size_t)b * S_LEN * D_MODEL + (size_t)h * HD;
    const __half* qp = g_q16 + base;
    const __half* kp = g_k16 + base;
    const __half* vp = g_v16 + base;
    __half* oph = g_o16 + base;

    // Q tile load (single group)
#pragma unroll
    for (int i = 0; i < 8; i++) {
        int idx = i * 128 + tid;
        int row = idx >> 4, ch = idx & 15;
        uint32_t dsw = SWZ256((uint32_t)(row * 256 + ch * 16));
        cp16(sb + FA_Q + dsw,
             (const char*)qp + (size_t)(q0 + row) * (D_MODEL * 2) + (size_t)ch * 16);
    }
    cp_commit();
    fa_issue_stage(sb, 0, 0, tid, kp, vp);
    fa_issue_stage(sb, 1, FAK < S_LEN ? FAK : 0, tid, kp, vp);

    const int g8 = lane >> 3;
    const int r8 = lane & 7;
    const int rowoff = (g8 & 1) * 8 + r8;
    const int qsel = g8 >> 1;

    // preload all Q fragments into registers (loop-invariant across kt)
    CP_WAIT(2);          // Q group complete
    __syncthreads();
    uint32_t qf[8][4];
#pragma unroll
    for (int ks = 0; ks < 8; ks++) {
        const int quad = ks * 2 + qsel;
        const uint32_t qoff = SWZ256((uint32_t)((w * 16 + rowoff) * 256 + quad * 16));
        ldsm_x4(qf[ks], sb + FA_Q + qoff);
    }

    float oacc[16][4];
#pragma unroll
    for (int t = 0; t < 16; t++) {
#pragma unroll
        for (int e = 0; e < 4; e++) { oacc[t][e] = 0.f; }
    }
    float m0 = -1e30f, m1 = -1e30f, l0 = 0.f, l1 = 0.f;
    const float sm_scale = 0.08838834764831843f;

    const int lrow0 = q0 + w * 16 + (lane >> 2);
    const int lcolb = (lane & 3) * 2;

    for (int kt = 0; kt < n_kt; kt++) {
        const int s = kt & 1;
        const int k0 = kt * FAK;
        CP_WAIT(1);
        __syncthreads();
        const uint32_t stg = sb + FA_STG + (uint32_t)s * FA_STAGE;

        // ---- S[16][64] = Q @ K^T : 1-pass fp16 ----
        float sacc[8][4];
#pragma unroll
        for (int t = 0; t < 8; t++) {
#pragma unroll
            for (int e = 0; e < 4; e++) { sacc[t][e] = 0.f; }
        }
#pragma unroll
        for (int ks = 0; ks < 8; ks++) {
#pragma unroll
            for (int nt = 0; nt < 4; nt++) {
                const uint32_t koff = SWZ256((uint32_t)((nt * 16 + rowoff) * 256 + (ks * 2 + qsel) * 16));
                uint32_t tk[4];
                ldsm_x4(tk, stg + koff);
                uint32_t b0[2], b1[2];
                b0[0] = tk[0]; b0[1] = tk[2];
                b1[0] = tk[1]; b1[1] = tk[3];
                mma_f16(sacc[nt * 2],     qf[ks], b0);
                mma_f16(sacc[nt * 2 + 1], qf[ks], b1);
            }
        }

        // ---- scale + causal mask ----
        const int need_mask = (k0 + FAK - 1 > q0 + w * 16) ? 1 : 0;
#pragma unroll
        for (int t = 0; t < 8; t++) {
#pragma unroll
            for (int e = 0; e < 4; e++) {
                float sv = sacc[t][e] * sm_scale;
                if (need_mask) {
                    int col = k0 + t * 8 + lcolb + (e & 1);
                    int row = lrow0 + ((e >> 1) & 1) * 8;
                    if (col > row) { sv = -1e30f; }
                }
                sacc[t][e] = sv;
            }
        }

        // ---- online softmax ----
        float rm0 = sacc[0][0], rm1 = sacc[0][2];
#pragma unroll
        for (int t = 0; t < 8; t++) {
            rm0 = fmaxf(rm0, fmaxf(sacc[t][0], sacc[t][1]));
            rm1 = fmaxf(rm1, fmaxf(sacc[t][2], sacc[t][3]));
        }
        rm0 = fmaxf(rm0, __shfl_xor_sync(0xffffffffu, rm0, 1));
        rm0 = fmaxf(rm0, __shfl_xor_sync(0xffffffffu, rm0, 2));
        rm1 = fmaxf(rm1, __shfl_xor_sync(0xffffffffu, rm1, 1));
        rm1 = fmaxf(rm1, __shfl_xor_sync(0xffffffffu, rm1, 2));
        float mn0 = fmaxf(m0, rm0);
        float mn1 = fmaxf(m1, rm1);
        float alpha0 = __expf(m0 - mn0);
        float alpha1 = __expf(m1 - mn1);
        float rs0 = 0.f, rs1 = 0.f;
#pragma unroll
        for (int t = 0; t < 8; t++) {
            float p0 = __expf(sacc[t][0] - mn0);
            float p1 = __expf(sacc[t][1] - mn0);
            float p2 = __expf(sacc[t][2] - mn1);
            float p3 = __expf(sacc[t][3] - mn1);
            rs0 += p0 + p1;
            rs1 += p2 + p3;
            sacc[t][0] = p0; sacc[t][1] = p1;
            sacc[t][2] = p2; sacc[t][3] = p3;
        }
        rs0 += __shfl_xor_sync(0xffffffffu, rs0, 1);
        rs0 += __shfl_xor_sync(0xffffffffu, rs0, 2);
        rs1 += __shfl_xor_sync(0xffffffffu, rs1, 1);
        rs1 += __shfl_xor_sync(0xffffffffu, rs1, 2);
        l0 = l0 * alpha0 + rs0;
        l1 = l1 * alpha1 + rs1;
        m0 = mn0; m1 = mn1;
#pragma unroll
        for (int t = 0; t < 16; t++) {
            oacc[t][0] *= alpha0; oacc[t][1] *= alpha0;
            oacc[t][2] *= alpha1; oacc[t][3] *= alpha1;
        }

        // ---- pack P[16][64] to fp16 A-frags (4 k-subtiles of 16) ----
        uint32_t pf[4][4];
#pragma unroll
        for (int j = 0; j < 4; j++) {
#pragma unroll
            for (int idx = 0; idx < 4; idx++) {
                int st = 2 * j + (idx >> 1);
                int rp = (idx & 1) * 2;
                __half p0 = __float2half_rn(sacc[st][rp]);
                __half p1 = __float2half_rn(sacc[st][rp + 1]);
                pf[j][idx] = (uint32_t)__half_as_ushort(p0)
                           | ((uint32_t)__half_as_ushort(p1) << 16);
            }
        }

        // ---- O += P @ V : single pass fp16, V 64 rows ----
        const int vrow_base = (lane & 7) + ((lane >> 3) & 1) * 8;
        const int vcol_base = ((lane >> 4) & 1) * 16;
#pragma unroll
        for (int j = 0; j < 4; j++) {
#pragma unroll
            for (int nt = 0; nt < 8; nt++) {
                const int vr = j * 16 + vrow_base;
                const int vcb = nt * 32 + vcol_base;
                const uint32_t voff = SWZ256((uint32_t)(vr * 256 + vcb));
                uint32_t tv[4];
                ldsm_x4_t(tv, stg + FA_TILE + voff);
                uint32_t b0[2], b1[2];
                b0[0] = tv[0]; b0[1] = tv[1];
                b1[0] = tv[2]; b1[1] = tv[3];
                mma_f16(oacc[nt * 2],     pf[j], b0);
                mma_f16(oacc[nt * 2 + 1], pf[j], b1);
            }
        }

        __syncthreads();
        if (kt + 2 < n_kt) {
            fa_issue_stage(sb, s, (kt + 2) * FAK, tid, kp, vp);
        } else {
            cp_commit();
        }
    }

    // ---- epilogue: normalize, store fp16 o ----
    const float inv0 = 1.f / l0;
    const float inv1 = 1.f / l1;
#pragma unroll
    for (int t = 0; t < 16; t++) {
        const int col = t * 8 + lcolb;
        const size_t off0 = (size_t)lrow0 * D_MODEL + col;
        const size_t off1 = (size_t)(lrow0 + 8) * D_MODEL + col;
        ushort2 a, bq;
        a.x = __half_as_ushort(__float2half_rn(oacc[t][0] * inv0));
        a.y = __half_as_ushort(__float2half_rn(oacc[t][1] * inv0));
        bq.x = __half_as_ushort(__float2half_rn(oacc[t][2] * inv1));
        bq.y = __half_as_ushort(__float2half_rn(oacc[t][3] * inv1));
        ((ushort2*)oph)[off0 >> 1] = a;
        ((ushort2*)oph)[off1 >> 1] = bq;
    }
}

// ======================= host side =======================
extern "C" void kernel_launch(void* const* d_in, const int* in_sizes, int n_in,
                              void* d_out, int out_size) {
    const float* x  = (const float*)d_in[0];
    const float* wq = (const float*)d_in[1];
    const float* wk = (const float*)d_in[2];
    const float* wv = (const float*)d_in[3];
    const float* wo = (const float*)d_in[4];
    float* out = (float*)d_out;

    __half *x16, *o16, *wo16;
    cudaGetSymbolAddress((void**)&x16, g_x16);
    cudaGetSymbolAddress((void**)&o16, g_o16);
    cudaGetSymbolAddress((void**)&wo16, g_wo16);

    rope_table_kernel<<<(S_LEN * (HD / 2) + 255) / 256, 256>>>();

    const int cvt_blocks = (CVT_TOTAL4 + 4 * 256 - 1) / (4 * 256);
    cvt_all_kernel<<<cvt_blocks, 256>>>(x, wq, wk, wv, wo);

    cudaFuncSetAttribute(gemm_qkv, cudaFuncAttributeMaxDynamicSharedMemorySize, GEMM_SMEM);
    cudaFuncSetAttribute(gemm_out, cudaFuncAttributeMaxDynamicSharedMemorySize, GEMM_SMEM);

    gemm_qkv<<<dim3(48, MROWS / GBM), 256, GEMM_SMEM>>>(x16);

    cudaFuncSetAttribute(flash_attn_mma, cudaFuncAttributeMaxDynamicSharedMemorySize, FA_SMEM);
    flash_attn_mma<<<dim3(S_LEN / FAQ, B_SZ * NH), 128, FA_SMEM>>>();

    gemm_out<<<dim3(16, MROWS / GBM), 256, GEMM_SMEM>>>(o16, wo16, out);
}